// round 1
// baseline (speedup 1.0000x reference)
#include <cuda_runtime.h>
#include <math.h>

// Problem constants: B=16, N=1024, C=768, H=12, HD=64, one mini-batch (m=1024)
#define NTOK   16384          // B*N
#define CDIM   768
#define NHEAD  12
#define HD     64
#define BH     192            // B*H
#define TOKHD  65536          // 1024*64 per (b,h)

// ---- scratch (static device globals; no allocations anywhere) ----
__device__ float g_Q[12582912];     // [B,H,N,HD]
__device__ float g_K[12582912];
__device__ float g_V[12582912];
__device__ float g_G[12582912];     // g = scaled LN-l2 backward grads
__device__ float g_XQW[12582912];   // [B,N,C] pre-projection
__device__ float g_eta[196608];     // [B,H,N]
__device__ float g_W1n[786432];     // [BH,64,64]
__device__ float g_b1n[12288];      // [BH,64]

__device__ __forceinline__ float warp_sum(float v) {
#pragma unroll
    for (int o = 16; o > 0; o >>= 1) v += __shfl_xor_sync(0xffffffffu, v, o);
    return v;
}

// ============================================================
// Kernel 1: QKV GEMM.  Y = x @ qkv_weight^T  (+bias), scattered
// into g_Q/g_K/g_V with [B,H,N,HD] layout.
// A: [16384,768] row-major, W: [2304,768] row-major (K contiguous both).
// Tiles 128x128x8, 256 threads, 8x8 per-thread micro-tile (2x2 of 4x4).
// ============================================================
__global__ __launch_bounds__(256) void qkv_gemm(
    const float* __restrict__ A, const float* __restrict__ W,
    const float* __restrict__ qb, const float* __restrict__ vb)
{
    __shared__ float As[8][132];
    __shared__ float Bs[8][132];
    const int K = CDIM;
    int m0 = blockIdx.y * 128, n0 = blockIdx.x * 128;
    int t = threadIdx.x;
    int tx = t & 15, ty = t >> 4;
    int lr = t >> 1, lk = (t & 1) * 4;
    float acc[2][2][4][4];
#pragma unroll
    for (int a = 0; a < 2; a++)
#pragma unroll
        for (int b = 0; b < 2; b++)
#pragma unroll
            for (int i = 0; i < 4; i++)
#pragma unroll
                for (int j = 0; j < 4; j++) acc[a][b][i][j] = 0.f;

    const float* Ap = A + (size_t)(m0 + lr) * K + lk;
    const float* Wp = W + (size_t)(n0 + lr) * K + lk;

    for (int k0 = 0; k0 < K; k0 += 8) {
        float4 av = *(const float4*)(Ap + k0);
        float4 bv = *(const float4*)(Wp + k0);
        __syncthreads();
        As[lk + 0][lr] = av.x; As[lk + 1][lr] = av.y;
        As[lk + 2][lr] = av.z; As[lk + 3][lr] = av.w;
        Bs[lk + 0][lr] = bv.x; Bs[lk + 1][lr] = bv.y;
        Bs[lk + 2][lr] = bv.z; Bs[lk + 3][lr] = bv.w;
        __syncthreads();
#pragma unroll
        for (int kk = 0; kk < 8; kk++) {
            float4 a0 = *(const float4*)&As[kk][ty * 4];
            float4 a1 = *(const float4*)&As[kk][64 + ty * 4];
            float4 b0 = *(const float4*)&Bs[kk][tx * 4];
            float4 b1 = *(const float4*)&Bs[kk][64 + tx * 4];
            float af[2][4] = {{a0.x, a0.y, a0.z, a0.w}, {a1.x, a1.y, a1.z, a1.w}};
            float bf[2][4] = {{b0.x, b0.y, b0.z, b0.w}, {b1.x, b1.y, b1.z, b1.w}};
#pragma unroll
            for (int hi = 0; hi < 2; hi++)
#pragma unroll
                for (int hj = 0; hj < 2; hj++)
#pragma unroll
                    for (int i = 0; i < 4; i++)
#pragma unroll
                        for (int j = 0; j < 4; j++)
                            acc[hi][hj][i][j] = fmaf(af[hi][i], bf[hj][j], acc[hi][hj][i][j]);
        }
    }

    // epilogue: scatter to Q/K/V [B,H,N,HD] with bias (k-bias is zero)
#pragma unroll
    for (int hi = 0; hi < 2; hi++)
#pragma unroll
        for (int i = 0; i < 4; i++) {
            int row = m0 + hi * 64 + ty * 4 + i;
            int b = row >> 10, n = row & 1023;
#pragma unroll
            for (int hj = 0; hj < 2; hj++)
#pragma unroll
                for (int j = 0; j < 4; j++) {
                    int col = n0 + hj * 64 + tx * 4 + j;
                    int which = col / 768;
                    int c = col - which * 768;
                    int h = c >> 6, d = c & 63;
                    int idx = ((b * NHEAD + h) << 16) + (n << 6) + d;
                    float v = acc[hi][hj][i][j];
                    if (which == 0)      g_Q[idx] = v + qb[c];
                    else if (which == 1) g_K[idx] = v;
                    else                 g_V[idx] = v + vb[c];
                }
        }
}

// ============================================================
// Kernel 2: per-token learned LR: eta = sigmoid(x·w_h + b_h)/64
// One block per token row, 12 warps = 12 heads.
// ============================================================
__global__ __launch_bounds__(384) void lr_kernel(
    const float* __restrict__ x, const float* __restrict__ lrw,
    const float* __restrict__ lrb)
{
    int row = blockIdx.x;                 // 0..16383
    __shared__ float xs[CDIM];
    int t = threadIdx.x;
    for (int i = t; i < CDIM; i += 384) xs[i] = x[(size_t)row * CDIM + i];
    __syncthreads();
    int h = t >> 5, l = t & 31;
    float s = 0.f;
    for (int c = l; c < CDIM; c += 32) s += xs[c] * lrw[h * CDIM + c];
    s = warp_sum(s);
    if (l == 0) {
        float v = 1.f / (1.f + expf(-(s + lrb[h])));
        int b = row >> 10, n = row & 1023;
        g_eta[(b * NHEAD + h) * 1024 + n] = v * (1.f / 64.f);
    }
}

// ============================================================
// Kernel 3: TTT phase 1.  Per (b,h): Z1 = XK@W1 + b1,
// g = ln_fused_l2_bwd(Z1, XV-XK) * eta/m  -> g_G, and b1n = b1 - sum g.
// 8 warps, warp-per-row (lane owns dims l and l+32).
// ============================================================
__global__ __launch_bounds__(256) void ttt_phase1(
    const float* __restrict__ W1, const float* __restrict__ b1,
    const float* __restrict__ gamma, const float* __restrict__ beta)
{
    int bh = blockIdx.x;
    int h = bh % NHEAD;
    __shared__ float W1s[4096];
    __shared__ float b1s[64], gs[64], bs[64];
    __shared__ float gbacc[8 * 64];
    int t = threadIdx.x;
    for (int i = t; i < 4096; i += 256) W1s[i] = W1[h * 4096 + i];
    if (t < 64) {
        b1s[t] = b1[h * 64 + t];
        gs[t]  = gamma[h * 64 + t];
        bs[t]  = beta[h * 64 + t];
    }
    __syncthreads();

    int w = t >> 5, l = t & 31;
    const float* Kp = g_K + (size_t)bh * TOKHD;
    const float* Vp = g_V + (size_t)bh * TOKHD;
    float* Gp = g_G + (size_t)bh * TOKHD;
    const float* etap = g_eta + bh * 1024;

    float gb0 = 0.f, gb1 = 0.f;
    for (int r = w; r < 1024; r += 8) {
        float xk0 = Kp[r * 64 + l], xk1 = Kp[r * 64 + l + 32];
        float z0 = b1s[l], z1 = b1s[l + 32];
#pragma unroll
        for (int c = 0; c < 64; c++) {
            float xc = __shfl_sync(0xffffffffu, (c < 32) ? xk0 : xk1, c & 31);
            z0 = fmaf(xc, W1s[c * 64 + l], z0);
            z1 = fmaf(xc, W1s[c * 64 + l + 32], z1);
        }
        // LN fused L2 backward
        float mu = warp_sum(z0 + z1) * (1.f / 64.f);
        float d0 = z0 - mu, d1 = z1 - mu;
        float var = warp_sum(d0 * d0 + d1 * d1) * (1.f / 64.f);
        float rstd = rsqrtf(var + 1e-6f);
        float xh0 = d0 * rstd, xh1 = d1 * rstd;
        float xv0 = Vp[r * 64 + l], xv1 = Vp[r * 64 + l + 32];
        float go0 = gs[l] * xh0 + bs[l] - (xv0 - xk0);
        float go1 = gs[l + 32] * xh1 + bs[l + 32] - (xv1 - xk1);
        float gg0 = go0 * gs[l], gg1 = go1 * gs[l + 32];
        float sg  = warp_sum(gg0 + gg1);
        float sgx = warp_sum(gg0 * xh0 + gg1 * xh1);
        float sc  = etap[r] * rstd * (1.f / 64.f) * (1.f / 1024.f);
        float gf0 = (64.f * gg0 - sg - xh0 * sgx) * sc;
        float gf1 = (64.f * gg1 - sg - xh1 * sgx) * sc;
        Gp[r * 64 + l] = gf0;
        Gp[r * 64 + l + 32] = gf1;
        gb0 += gf0; gb1 += gf1;
    }
    gbacc[w * 64 + l] = gb0;
    gbacc[w * 64 + l + 32] = gb1;
    __syncthreads();
    if (t < 64) {
        float s = 0.f;
#pragma unroll
        for (int ww = 0; ww < 8; ww++) s += gbacc[ww * 64 + t];
        g_b1n[bh * 64 + t] = b1s[t] - s;
    }
}

// ============================================================
// Kernel 4: W1n = W1 - XK^T @ g  (64x64, K=1024). One block per (b,h).
// 256 threads, 4x4 outputs each, K tiled by 32 through smem.
// ============================================================
__global__ __launch_bounds__(256) void ttt_gradw(const float* __restrict__ W1)
{
    int bh = blockIdx.x;
    int h = bh % NHEAD;
    __shared__ float Ks[32][68];
    __shared__ float Gs[32][68];
    int t = threadIdx.x;
    int tx = t & 15, ty = t >> 4;
    int lr = t >> 3, lc = (t & 7) * 8;
    float acc[4][4];
#pragma unroll
    for (int i = 0; i < 4; i++)
#pragma unroll
        for (int j = 0; j < 4; j++) acc[i][j] = 0.f;

    const float* Kp = g_K + (size_t)bh * TOKHD;
    const float* Gp = g_G + (size_t)bh * TOKHD;

    for (int k0 = 0; k0 < 1024; k0 += 32) {
        float4 kv0 = *(const float4*)(Kp + (k0 + lr) * 64 + lc);
        float4 kv1 = *(const float4*)(Kp + (k0 + lr) * 64 + lc + 4);
        float4 gv0 = *(const float4*)(Gp + (k0 + lr) * 64 + lc);
        float4 gv1 = *(const float4*)(Gp + (k0 + lr) * 64 + lc + 4);
        __syncthreads();
        *(float4*)&Ks[lr][lc]     = kv0;
        *(float4*)&Ks[lr][lc + 4] = kv1;
        *(float4*)&Gs[lr][lc]     = gv0;
        *(float4*)&Gs[lr][lc + 4] = gv1;
        __syncthreads();
#pragma unroll
        for (int r = 0; r < 32; r++) {
            float4 a = *(const float4*)&Ks[r][ty * 4];
            float4 b = *(const float4*)&Gs[r][tx * 4];
            float af[4] = {a.x, a.y, a.z, a.w};
            float bf[4] = {b.x, b.y, b.z, b.w};
#pragma unroll
            for (int i = 0; i < 4; i++)
#pragma unroll
                for (int j = 0; j < 4; j++)
                    acc[i][j] = fmaf(af[i], bf[j], acc[i][j]);
        }
    }
#pragma unroll
    for (int i = 0; i < 4; i++)
#pragma unroll
        for (int j = 0; j < 4; j++) {
            int d = ty * 4 + i, e = tx * 4 + j;
            g_W1n[bh * 4096 + d * 64 + e] = W1[h * 4096 + d * 64 + e] - acc[i][j];
        }
}

// ============================================================
// Kernel 5: Z1_bar = ln_fwd(XQ@W1n + b1n); out = XQ + Z1_bar
// written as [B,N,C] into g_XQW for the projection GEMM.
// ============================================================
__global__ __launch_bounds__(256) void ttt_phase3(
    const float* __restrict__ gamma, const float* __restrict__ beta)
{
    int bh = blockIdx.x;
    int h = bh % NHEAD, b = bh / NHEAD;
    __shared__ float W1s[4096];
    __shared__ float b1s[64], gs[64], bs[64];
    int t = threadIdx.x;
    for (int i = t; i < 4096; i += 256) W1s[i] = g_W1n[bh * 4096 + i];
    if (t < 64) {
        b1s[t] = g_b1n[bh * 64 + t];
        gs[t]  = gamma[h * 64 + t];
        bs[t]  = beta[h * 64 + t];
    }
    __syncthreads();

    int w = t >> 5, l = t & 31;
    const float* Qp = g_Q + (size_t)bh * TOKHD;
    float* Op = g_XQW + (size_t)b * 1024 * CDIM;

    for (int r = w; r < 1024; r += 8) {
        float xq0 = Qp[r * 64 + l], xq1 = Qp[r * 64 + l + 32];
        float z0 = b1s[l], z1 = b1s[l + 32];
#pragma unroll
        for (int c = 0; c < 64; c++) {
            float xc = __shfl_sync(0xffffffffu, (c < 32) ? xq0 : xq1, c & 31);
            z0 = fmaf(xc, W1s[c * 64 + l], z0);
            z1 = fmaf(xc, W1s[c * 64 + l + 32], z1);
        }
        float mu = warp_sum(z0 + z1) * (1.f / 64.f);
        float d0 = z0 - mu, d1 = z1 - mu;
        float var = warp_sum(d0 * d0 + d1 * d1) * (1.f / 64.f);
        float rstd = rsqrtf(var + 1e-6f);
        float y0 = gs[l] * (d0 * rstd) + bs[l];
        float y1 = gs[l + 32] * (d1 * rstd) + bs[l + 32];
        Op[r * CDIM + h * 64 + l]      = xq0 + y0;
        Op[r * CDIM + h * 64 + l + 32] = xq1 + y1;
    }
}

// ============================================================
// Kernel 6: projection GEMM.  out = XQW @ proj_weight^T + proj_bias
// Same tiling as qkv_gemm.
// ============================================================
__global__ __launch_bounds__(256) void proj_gemm(
    const float* __restrict__ W, const float* __restrict__ pb,
    float* __restrict__ out)
{
    __shared__ float As[8][132];
    __shared__ float Bs[8][132];
    const int K = CDIM;
    int m0 = blockIdx.y * 128, n0 = blockIdx.x * 128;
    int t = threadIdx.x;
    int tx = t & 15, ty = t >> 4;
    int lr = t >> 1, lk = (t & 1) * 4;
    float acc[2][2][4][4];
#pragma unroll
    for (int a = 0; a < 2; a++)
#pragma unroll
        for (int b = 0; b < 2; b++)
#pragma unroll
            for (int i = 0; i < 4; i++)
#pragma unroll
                for (int j = 0; j < 4; j++) acc[a][b][i][j] = 0.f;

    const float* Ap = g_XQW + (size_t)(m0 + lr) * K + lk;
    const float* Wp = W + (size_t)(n0 + lr) * K + lk;

    for (int k0 = 0; k0 < K; k0 += 8) {
        float4 av = *(const float4*)(Ap + k0);
        float4 bv = *(const float4*)(Wp + k0);
        __syncthreads();
        As[lk + 0][lr] = av.x; As[lk + 1][lr] = av.y;
        As[lk + 2][lr] = av.z; As[lk + 3][lr] = av.w;
        Bs[lk + 0][lr] = bv.x; Bs[lk + 1][lr] = bv.y;
        Bs[lk + 2][lr] = bv.z; Bs[lk + 3][lr] = bv.w;
        __syncthreads();
#pragma unroll
        for (int kk = 0; kk < 8; kk++) {
            float4 a0 = *(const float4*)&As[kk][ty * 4];
            float4 a1 = *(const float4*)&As[kk][64 + ty * 4];
            float4 b0 = *(const float4*)&Bs[kk][tx * 4];
            float4 b1 = *(const float4*)&Bs[kk][64 + tx * 4];
            float af[2][4] = {{a0.x, a0.y, a0.z, a0.w}, {a1.x, a1.y, a1.z, a1.w}};
            float bf[2][4] = {{b0.x, b0.y, b0.z, b0.w}, {b1.x, b1.y, b1.z, b1.w}};
#pragma unroll
            for (int hi = 0; hi < 2; hi++)
#pragma unroll
                for (int hj = 0; hj < 2; hj++)
#pragma unroll
                    for (int i = 0; i < 4; i++)
#pragma unroll
                        for (int j = 0; j < 4; j++)
                            acc[hi][hj][i][j] = fmaf(af[hi][i], bf[hj][j], acc[hi][hj][i][j]);
        }
    }

#pragma unroll
    for (int hi = 0; hi < 2; hi++)
#pragma unroll
        for (int i = 0; i < 4; i++) {
            int row = m0 + hi * 64 + ty * 4 + i;
#pragma unroll
            for (int hj = 0; hj < 2; hj++)
#pragma unroll
                for (int j = 0; j < 4; j++) {
                    int col = n0 + hj * 64 + tx * 4 + j;
                    out[(size_t)row * CDIM + col] = acc[hi][hj][i][j] + pb[col];
                }
        }
}

// ============================================================
extern "C" void kernel_launch(void* const* d_in, const int* in_sizes, int n_in,
                              void* d_out, int out_size)
{
    (void)in_sizes; (void)n_in; (void)out_size;
    const float* x     = (const float*)d_in[0];
    const float* qkvw  = (const float*)d_in[1];
    const float* qb    = (const float*)d_in[2];
    const float* vb    = (const float*)d_in[3];
    const float* pw    = (const float*)d_in[4];
    const float* pb    = (const float*)d_in[5];
    const float* lrw   = (const float*)d_in[6];
    const float* lrb   = (const float*)d_in[7];
    const float* gamma = (const float*)d_in[8];
    const float* beta  = (const float*)d_in[9];
    const float* W1    = (const float*)d_in[10];
    const float* b1    = (const float*)d_in[11];
    float* out = (float*)d_out;

    qkv_gemm<<<dim3(18, 128), 256>>>(x, qkvw, qb, vb);
    lr_kernel<<<16384, 384>>>(x, lrw, lrb);
    ttt_phase1<<<192, 256>>>(W1, b1, gamma, beta);
    ttt_gradw<<<192, 256>>>(W1);
    ttt_phase3<<<192, 256>>>(gamma, beta);
    proj_gemm<<<dim3(6, 128), 256>>>(pw, pb, out);
}

// round 2
// speedup vs baseline: 1.1947x; 1.1947x over previous
#include <cuda_runtime.h>
#include <mma.h>
#include <math.h>

using namespace nvcuda;

// Problem constants: B=16, N=1024, C=768, H=12, HD=64, one mini-batch (m=1024)
#define NTOK   16384
#define CDIM   768
#define NHEAD  12
#define HD     64
#define BH     192
#define TOKHD  65536          // 1024*64 per (b,h)

// ---- scratch (static device globals; no allocations anywhere) ----
__device__ float g_Q[12582912];     // [B,H,N,HD]
__device__ float g_K[12582912];
__device__ float g_V[12582912];
__device__ float g_G[12582912];     // g = scaled LN-l2 backward grads
__device__ float g_XQW[12582912];   // [B,N,C] pre-projection
__device__ float g_eta[196608];     // [B,H,N]
__device__ float g_W1n[786432];     // [BH,64,64]
__device__ float g_b1n[12288];      // [BH,64]

__device__ __forceinline__ float warp_sum(float v) {
#pragma unroll
    for (int o = 16; o > 0; o >>= 1) v += __shfl_xor_sync(0xffffffffu, v, o);
    return v;
}

// ============================================================
// Kernel 1: QKV GEMM on tensor cores (tf32 wmma, 128x128x32 tiles).
// Y = x @ qkv_weight^T + bias, stored DIRECTLY into g_Q/g_K/g_V
// [B,H,N,64] layout via fragment stores (all tile boundaries are
// multiples of 16, so a 16x16 fragment never crosses head/which/batch).
// Bias enters via accumulator-init from a shared bias tile.
// ============================================================
__global__ __launch_bounds__(256) void qkv_gemm_tc(
    const float* __restrict__ A, const float* __restrict__ W,
    const float* __restrict__ qb, const float* __restrict__ vb)
{
    __shared__ float As[128][36];
    __shared__ float Bs[128][36];
    __shared__ float bias2d[16][132];

    const int K = CDIM;
    int m0 = blockIdx.y * 128, n0 = blockIdx.x * 128;
    int t = threadIdx.x;
    int w = t >> 5;
    int wy = w >> 2, wx = w & 3;   // warp tile: 64(m) x 32(n)

    // build bias tile: 16 identical rows, value = combined qkv bias[col]
    if (t < 128) {
        int col = n0 + t;
        int which = col / 768, c = col - which * 768;
        float bv = (which == 0) ? qb[c] : ((which == 2) ? vb[c] : 0.f);
#pragma unroll
        for (int r = 0; r < 16; r++) bias2d[r][t] = bv;
    }
    __syncthreads();

    wmma::fragment<wmma::accumulator, 16, 16, 8, float> acc[4][2];
#pragma unroll
    for (int i = 0; i < 4; i++)
#pragma unroll
        for (int j = 0; j < 2; j++)
            wmma::load_matrix_sync(acc[i][j], &bias2d[0][wx * 32 + j * 16], 132,
                                   wmma::mem_row_major);

    for (int k0 = 0; k0 < K; k0 += 32) {
        __syncthreads();
#pragma unroll
        for (int i = 0; i < 4; i++) {
            int idx = t + i * 256;
            int row = idx >> 3, c4 = (idx & 7) * 4;
            *(float4*)&As[row][c4] =
                *(const float4*)&A[(size_t)(m0 + row) * K + k0 + c4];
            *(float4*)&Bs[row][c4] =
                *(const float4*)&W[(size_t)(n0 + row) * K + k0 + c4];
        }
        __syncthreads();
#pragma unroll
        for (int kk = 0; kk < 32; kk += 8) {
            wmma::fragment<wmma::matrix_a, 16, 16, 8, wmma::precision::tf32,
                           wmma::row_major> af[4];
            wmma::fragment<wmma::matrix_b, 16, 16, 8, wmma::precision::tf32,
                           wmma::col_major> bf[2];
#pragma unroll
            for (int i = 0; i < 4; i++) {
                wmma::load_matrix_sync(af[i], &As[wy * 64 + i * 16][kk], 36);
#pragma unroll
                for (int e = 0; e < af[i].num_elements; e++)
                    af[i].x[e] = wmma::__float_to_tf32(af[i].x[e]);
            }
#pragma unroll
            for (int j = 0; j < 2; j++) {
                wmma::load_matrix_sync(bf[j], &Bs[wx * 32 + j * 16][kk], 36);
#pragma unroll
                for (int e = 0; e < bf[j].num_elements; e++)
                    bf[j].x[e] = wmma::__float_to_tf32(bf[j].x[e]);
            }
#pragma unroll
            for (int i = 0; i < 4; i++)
#pragma unroll
                for (int j = 0; j < 2; j++)
                    wmma::mma_sync(acc[i][j], af[i], bf[j], acc[i][j]);
        }
    }

    // scatter-store: each 16x16 fragment goes straight into Q/K/V [B,H,N,64]
#pragma unroll
    for (int i = 0; i < 4; i++) {
        int row0 = m0 + wy * 64 + i * 16;
        int b = row0 >> 10, n = row0 & 1023;
#pragma unroll
        for (int j = 0; j < 2; j++) {
            int col0 = n0 + wx * 32 + j * 16;
            int which = col0 / 768;
            int c = col0 - which * 768;
            int h = c >> 6, d0 = c & 63;
            float* dst = (which == 0 ? g_Q : (which == 1 ? g_K : g_V))
                         + ((size_t)(b * NHEAD + h) << 16) + (n << 6) + d0;
            wmma::store_matrix_sync(dst, acc[i][j], 64, wmma::mem_row_major);
        }
    }
}

// ============================================================
// Kernel 2: per-token learned LR: eta = sigmoid(x·w_h + b_h)/64
// ============================================================
__global__ __launch_bounds__(384) void lr_kernel(
    const float* __restrict__ x, const float* __restrict__ lrw,
    const float* __restrict__ lrb)
{
    int row = blockIdx.x;
    __shared__ float xs[CDIM];
    int t = threadIdx.x;
    for (int i = t; i < CDIM; i += 384) xs[i] = x[(size_t)row * CDIM + i];
    __syncthreads();
    int h = t >> 5, l = t & 31;
    float s = 0.f;
    for (int c = l; c < CDIM; c += 32) s += xs[c] * lrw[h * CDIM + c];
    s = warp_sum(s);
    if (l == 0) {
        float v = 1.f / (1.f + expf(-(s + lrb[h])));
        int b = row >> 10, n = row & 1023;
        g_eta[(b * NHEAD + h) * 1024 + n] = v * (1.f / 64.f);
    }
}

// ============================================================
// Kernel 3: TTT phase 1. Per (b,h): Z1 = XK@W1+b1,
// g = ln_fused_l2_bwd(Z1, XV-XK) * eta/m -> g_G, and b1n = b1 - sum g.
// ============================================================
__global__ __launch_bounds__(256) void ttt_phase1(
    const float* __restrict__ W1, const float* __restrict__ b1,
    const float* __restrict__ gamma, const float* __restrict__ beta)
{
    int bh = blockIdx.x;
    int h = bh % NHEAD;
    __shared__ float W1s[4096];
    __shared__ float b1s[64], gs[64], bs[64];
    __shared__ float gbacc[8 * 64];
    int t = threadIdx.x;
    for (int i = t; i < 4096; i += 256) W1s[i] = W1[h * 4096 + i];
    if (t < 64) {
        b1s[t] = b1[h * 64 + t];
        gs[t]  = gamma[h * 64 + t];
        bs[t]  = beta[h * 64 + t];
    }
    __syncthreads();

    int w = t >> 5, l = t & 31;
    const float* Kp = g_K + (size_t)bh * TOKHD;
    const float* Vp = g_V + (size_t)bh * TOKHD;
    float* Gp = g_G + (size_t)bh * TOKHD;
    const float* etap = g_eta + bh * 1024;

    float gb0 = 0.f, gb1 = 0.f;
    for (int r = w; r < 1024; r += 8) {
        float xk0 = Kp[r * 64 + l], xk1 = Kp[r * 64 + l + 32];
        float z0 = b1s[l], z1 = b1s[l + 32];
#pragma unroll
        for (int c = 0; c < 64; c++) {
            float xc = __shfl_sync(0xffffffffu, (c < 32) ? xk0 : xk1, c & 31);
            z0 = fmaf(xc, W1s[c * 64 + l], z0);
            z1 = fmaf(xc, W1s[c * 64 + l + 32], z1);
        }
        float mu = warp_sum(z0 + z1) * (1.f / 64.f);
        float d0 = z0 - mu, d1 = z1 - mu;
        float var = warp_sum(d0 * d0 + d1 * d1) * (1.f / 64.f);
        float rstd = rsqrtf(var + 1e-6f);
        float xh0 = d0 * rstd, xh1 = d1 * rstd;
        float xv0 = Vp[r * 64 + l], xv1 = Vp[r * 64 + l + 32];
        float go0 = gs[l] * xh0 + bs[l] - (xv0 - xk0);
        float go1 = gs[l + 32] * xh1 + bs[l + 32] - (xv1 - xk1);
        float gg0 = go0 * gs[l], gg1 = go1 * gs[l + 32];
        float sg  = warp_sum(gg0 + gg1);
        float sgx = warp_sum(gg0 * xh0 + gg1 * xh1);
        float sc  = etap[r] * rstd * (1.f / 64.f) * (1.f / 1024.f);
        float gf0 = (64.f * gg0 - sg - xh0 * sgx) * sc;
        float gf1 = (64.f * gg1 - sg - xh1 * sgx) * sc;
        Gp[r * 64 + l] = gf0;
        Gp[r * 64 + l + 32] = gf1;
        gb0 += gf0; gb1 += gf1;
    }
    gbacc[w * 64 + l] = gb0;
    gbacc[w * 64 + l + 32] = gb1;
    __syncthreads();
    if (t < 64) {
        float s = 0.f;
#pragma unroll
        for (int ww = 0; ww < 8; ww++) s += gbacc[ww * 64 + t];
        g_b1n[bh * 64 + t] = b1s[t] - s;
    }
}

// ============================================================
// Kernel 4: W1n = W1 - XK^T @ g  (64x64, K=1024). One block per (b,h).
// ============================================================
__global__ __launch_bounds__(256) void ttt_gradw(const float* __restrict__ W1)
{
    int bh = blockIdx.x;
    int h = bh % NHEAD;
    __shared__ float Ks[32][68];
    __shared__ float Gs[32][68];
    int t = threadIdx.x;
    int tx = t & 15, ty = t >> 4;
    int lr = t >> 3, lc = (t & 7) * 8;
    float acc[4][4];
#pragma unroll
    for (int i = 0; i < 4; i++)
#pragma unroll
        for (int j = 0; j < 4; j++) acc[i][j] = 0.f;

    const float* Kp = g_K + (size_t)bh * TOKHD;
    const float* Gp = g_G + (size_t)bh * TOKHD;

    for (int k0 = 0; k0 < 1024; k0 += 32) {
        float4 kv0 = *(const float4*)(Kp + (k0 + lr) * 64 + lc);
        float4 kv1 = *(const float4*)(Kp + (k0 + lr) * 64 + lc + 4);
        float4 gv0 = *(const float4*)(Gp + (k0 + lr) * 64 + lc);
        float4 gv1 = *(const float4*)(Gp + (k0 + lr) * 64 + lc + 4);
        __syncthreads();
        *(float4*)&Ks[lr][lc]     = kv0;
        *(float4*)&Ks[lr][lc + 4] = kv1;
        *(float4*)&Gs[lr][lc]     = gv0;
        *(float4*)&Gs[lr][lc + 4] = gv1;
        __syncthreads();
#pragma unroll
        for (int r = 0; r < 32; r++) {
            float4 a = *(const float4*)&Ks[r][ty * 4];
            float4 b = *(const float4*)&Gs[r][tx * 4];
            float af[4] = {a.x, a.y, a.z, a.w};
            float bf[4] = {b.x, b.y, b.z, b.w};
#pragma unroll
            for (int i = 0; i < 4; i++)
#pragma unroll
                for (int j = 0; j < 4; j++)
                    acc[i][j] = fmaf(af[i], bf[j], acc[i][j]);
        }
    }
#pragma unroll
    for (int i = 0; i < 4; i++)
#pragma unroll
        for (int j = 0; j < 4; j++) {
            int d = ty * 4 + i, e = tx * 4 + j;
            g_W1n[bh * 4096 + d * 64 + e] = W1[h * 4096 + d * 64 + e] - acc[i][j];
        }
}

// ============================================================
// Kernel 5: Z1_bar = ln_fwd(XQ@W1n + b1n); out = XQ + Z1_bar -> g_XQW [B,N,C]
// ============================================================
__global__ __launch_bounds__(256) void ttt_phase3(
    const float* __restrict__ gamma, const float* __restrict__ beta)
{
    int bh = blockIdx.x;
    int h = bh % NHEAD, b = bh / NHEAD;
    __shared__ float W1s[4096];
    __shared__ float b1s[64], gs[64], bs[64];
    int t = threadIdx.x;
    for (int i = t; i < 4096; i += 256) W1s[i] = g_W1n[bh * 4096 + i];
    if (t < 64) {
        b1s[t] = g_b1n[bh * 64 + t];
        gs[t]  = gamma[h * 64 + t];
        bs[t]  = beta[h * 64 + t];
    }
    __syncthreads();

    int w = t >> 5, l = t & 31;
    const float* Qp = g_Q + (size_t)bh * TOKHD;
    float* Op = g_XQW + (size_t)b * 1024 * CDIM;

    for (int r = w; r < 1024; r += 8) {
        float xq0 = Qp[r * 64 + l], xq1 = Qp[r * 64 + l + 32];
        float z0 = b1s[l], z1 = b1s[l + 32];
#pragma unroll
        for (int c = 0; c < 64; c++) {
            float xc = __shfl_sync(0xffffffffu, (c < 32) ? xq0 : xq1, c & 31);
            z0 = fmaf(xc, W1s[c * 64 + l], z0);
            z1 = fmaf(xc, W1s[c * 64 + l + 32], z1);
        }
        float mu = warp_sum(z0 + z1) * (1.f / 64.f);
        float d0 = z0 - mu, d1 = z1 - mu;
        float var = warp_sum(d0 * d0 + d1 * d1) * (1.f / 64.f);
        float rstd = rsqrtf(var + 1e-6f);
        float y0 = gs[l] * (d0 * rstd) + bs[l];
        float y1 = gs[l + 32] * (d1 * rstd) + bs[l + 32];
        Op[r * CDIM + h * 64 + l]      = xq0 + y0;
        Op[r * CDIM + h * 64 + l + 32] = xq1 + y1;
    }
}

// ============================================================
// Kernel 6: projection GEMM on tensor cores.
// out = XQW @ proj_weight^T + proj_bias (bias via accumulator init)
// ============================================================
__global__ __launch_bounds__(256) void proj_gemm_tc(
    const float* __restrict__ W, const float* __restrict__ pb,
    float* __restrict__ out)
{
    __shared__ float As[128][36];
    __shared__ float Bs[128][36];
    __shared__ float bias2d[16][132];

    const int K = CDIM;
    const int N = CDIM;
    int m0 = blockIdx.y * 128, n0 = blockIdx.x * 128;
    int t = threadIdx.x;
    int w = t >> 5;
    int wy = w >> 2, wx = w & 3;

    if (t < 128) {
        float bv = pb[n0 + t];
#pragma unroll
        for (int r = 0; r < 16; r++) bias2d[r][t] = bv;
    }
    __syncthreads();

    wmma::fragment<wmma::accumulator, 16, 16, 8, float> acc[4][2];
#pragma unroll
    for (int i = 0; i < 4; i++)
#pragma unroll
        for (int j = 0; j < 2; j++)
            wmma::load_matrix_sync(acc[i][j], &bias2d[0][wx * 32 + j * 16], 132,
                                   wmma::mem_row_major);

    for (int k0 = 0; k0 < K; k0 += 32) {
        __syncthreads();
#pragma unroll
        for (int i = 0; i < 4; i++) {
            int idx = t + i * 256;
            int row = idx >> 3, c4 = (idx & 7) * 4;
            *(float4*)&As[row][c4] =
                *(const float4*)&g_XQW[(size_t)(m0 + row) * K + k0 + c4];
            *(float4*)&Bs[row][c4] =
                *(const float4*)&W[(size_t)(n0 + row) * K + k0 + c4];
        }
        __syncthreads();
#pragma unroll
        for (int kk = 0; kk < 32; kk += 8) {
            wmma::fragment<wmma::matrix_a, 16, 16, 8, wmma::precision::tf32,
                           wmma::row_major> af[4];
            wmma::fragment<wmma::matrix_b, 16, 16, 8, wmma::precision::tf32,
                           wmma::col_major> bf[2];
#pragma unroll
            for (int i = 0; i < 4; i++) {
                wmma::load_matrix_sync(af[i], &As[wy * 64 + i * 16][kk], 36);
#pragma unroll
                for (int e = 0; e < af[i].num_elements; e++)
                    af[i].x[e] = wmma::__float_to_tf32(af[i].x[e]);
            }
#pragma unroll
            for (int j = 0; j < 2; j++) {
                wmma::load_matrix_sync(bf[j], &Bs[wx * 32 + j * 16][kk], 36);
#pragma unroll
                for (int e = 0; e < bf[j].num_elements; e++)
                    bf[j].x[e] = wmma::__float_to_tf32(bf[j].x[e]);
            }
#pragma unroll
            for (int i = 0; i < 4; i++)
#pragma unroll
                for (int j = 0; j < 2; j++)
                    wmma::mma_sync(acc[i][j], af[i], bf[j], acc[i][j]);
        }
    }

#pragma unroll
    for (int i = 0; i < 4; i++) {
        int row0 = m0 + wy * 64 + i * 16;
#pragma unroll
        for (int j = 0; j < 2; j++) {
            int col0 = n0 + wx * 32 + j * 16;
            wmma::store_matrix_sync(out + (size_t)row0 * N + col0, acc[i][j], N,
                                    wmma::mem_row_major);
        }
    }
}

// ============================================================
extern "C" void kernel_launch(void* const* d_in, const int* in_sizes, int n_in,
                              void* d_out, int out_size)
{
    (void)in_sizes; (void)n_in; (void)out_size;
    const float* x     = (const float*)d_in[0];
    const float* qkvw  = (const float*)d_in[1];
    const float* qb    = (const float*)d_in[2];
    const float* vb    = (const float*)d_in[3];
    const float* pw    = (const float*)d_in[4];
    const float* pb    = (const float*)d_in[5];
    const float* lrw   = (const float*)d_in[6];
    const float* lrb   = (const float*)d_in[7];
    const float* gamma = (const float*)d_in[8];
    const float* beta  = (const float*)d_in[9];
    const float* W1    = (const float*)d_in[10];
    const float* b1    = (const float*)d_in[11];
    float* out = (float*)d_out;

    qkv_gemm_tc<<<dim3(18, 128), 256>>>(x, qkvw, qb, vb);
    lr_kernel<<<16384, 384>>>(x, lrw, lrb);
    ttt_phase1<<<192, 256>>>(W1, b1, gamma, beta);
    ttt_gradw<<<192, 256>>>(W1);
    ttt_phase3<<<192, 256>>>(gamma, beta);
    proj_gemm_tc<<<dim3(6, 128), 256>>>(pw, pb, out);
}

// round 4
// speedup vs baseline: 2.3630x; 1.9779x over previous
#include <cuda_runtime.h>
#include <cuda_fp16.h>
#include <mma.h>
#include <math.h>
#include <stdint.h>

using namespace nvcuda;

// Problem constants: B=16, N=1024, C=768, H=12, HD=64, one mini-batch (m=1024)
#define NTOK   16384
#define CDIM   768
#define NHEAD  12
#define HD     64
#define BH     192
#define TOKHD  65536          // 1024*64 per (b,h)

// ---- scratch (static device globals; no allocations anywhere) ----
__device__ float  g_Q[12582912];     // [B,H,N,HD]
__device__ float  g_K[12582912];
__device__ float  g_V[12582912];
__device__ float  g_G[12582912];     // g = scaled LN-l2 backward grads
__device__ float  g_eta[196608];     // [B,H,N]
__device__ float  g_W1n[786432];     // [BH,64,64]
__device__ float  g_b1n[12288];      // [BH,64]
__device__ __half g_Xh[12582912];    // half(x) [16384,768]
__device__ __half g_Wqh[1769472];    // half(qkv_weight) [2304,768]
__device__ __half g_Wph[589824];     // half(proj_weight) [768,768]
__device__ __half g_XQWh[12582912];  // half pre-projection [B,N,C]

__device__ __forceinline__ float warp_sum(float v) {
#pragma unroll
    for (int o = 16; o > 0; o >>= 1) v += __shfl_xor_sync(0xffffffffu, v, o);
    return v;
}

__device__ __forceinline__ uint32_t smem_u32(const void* p) {
    uint32_t a;
    asm("{ .reg .u64 t; cvta.to.shared.u64 t, %1; cvt.u32.u64 %0, t; }"
        : "=r"(a) : "l"(p));
    return a;
}
__device__ __forceinline__ void cp16(uint32_t dst, const void* src) {
    asm volatile("cp.async.cg.shared.global [%0], [%1], 16;" :: "r"(dst), "l"(src));
}
__device__ __forceinline__ void cp_commit() {
    asm volatile("cp.async.commit_group;" ::: "memory");
}
template <int N> __device__ __forceinline__ void cp_wait() {
    asm volatile("cp.async.wait_group %0;" :: "n"(N) : "memory");
}

// ============================================================
// fp32 -> fp16 conversion pass (half2 stores)
// ============================================================
__global__ void f2h_pass(const float* __restrict__ in, __half* __restrict__ out, int n2)
{
    int i = blockIdx.x * blockDim.x + threadIdx.x;
    if (i < n2) {
        float2 v = ((const float2*)in)[i];
        ((__half2*)out)[i] = __floats2half2_rn(v.x, v.y);
    }
}

// ============================================================
// fp16 wmma GEMM: C[M,N] = A[M,768] @ W[N,768]^T (+bias)
// Tile 128x128, 256 threads (8 warps, warp tile 64x32),
// K chunks of 64 halfs, cp.async double-buffered smem.
// MODE 0: scatter into g_Q/g_K/g_V [B,H,N,64] (+q/v bias)
// MODE 1: direct store to outp [M,768] (+proj bias)
// dynamic smem: A[2][128][72] halfs + B[2][128][72] halfs = 73728 B
// ============================================================
#define LDS_PAD 72
#define CHUNK_HALFS (128 * LDS_PAD)      // per buffer, halfs
#define GEMM_SMEM (4 * CHUNK_HALFS * 2)  // bytes

template <int MODE>
__global__ __launch_bounds__(256) void gemm_fp16(
    const __half* __restrict__ A, const __half* __restrict__ Bw,
    const float* __restrict__ bias0, const float* __restrict__ bias1,
    float* __restrict__ outp)
{
    extern __shared__ __half hsm[];
    __half* Abuf[2] = {hsm, hsm + CHUNK_HALFS};
    __half* Bbuf[2] = {hsm + 2 * CHUNK_HALFS, hsm + 3 * CHUNK_HALFS};
    __shared__ float bias2d[16][132];

    int t = threadIdx.x;
    int w = t >> 5;
    int wy = w >> 2, wx = w & 3;      // warp tile 64(m) x 32(n)
    int m0 = blockIdx.y * 128, n0 = blockIdx.x * 128;

    // bias tile (16 identical rows)
    if (t < 128) {
        int col = n0 + t;
        float bv;
        if (MODE == 0) {
            int which = col / 768, c = col - which * 768;
            bv = (which == 0) ? bias0[c] : ((which == 2) ? bias1[c] : 0.f);
        } else bv = bias0[col];
#pragma unroll
        for (int r = 0; r < 16; r++) bias2d[r][t] = bv;
    }
    __syncthreads();

    wmma::fragment<wmma::accumulator, 16, 16, 16, float> acc[4][2];
#pragma unroll
    for (int i = 0; i < 4; i++)
#pragma unroll
        for (int j = 0; j < 2; j++)
            wmma::load_matrix_sync(acc[i][j], &bias2d[0][wx * 32 + j * 16], 132,
                                   wmma::mem_row_major);

    const __half* gA = A + (size_t)m0 * 768;
    const __half* gB = Bw + (size_t)n0 * 768;

    uint32_t aS[2] = {smem_u32(Abuf[0]), smem_u32(Abuf[1])};
    uint32_t bS[2] = {smem_u32(Bbuf[0]), smem_u32(Bbuf[1])};

    auto load_chunk = [&](int kc, int p) {
#pragma unroll
        for (int j = 0; j < 4; j++) {
            int s = t + j * 256;            // 0..1023
            int row = s >> 3, c8 = s & 7;   // 128 rows x 8 groups of 8 halfs
            cp16(aS[p] + row * (LDS_PAD * 2) + c8 * 16,
                 gA + (size_t)row * 768 + kc * 64 + c8 * 8);
            cp16(bS[p] + row * (LDS_PAD * 2) + c8 * 16,
                 gB + (size_t)row * 768 + kc * 64 + c8 * 8);
        }
        cp_commit();
    };

    load_chunk(0, 0);
    const int NCHUNK = 12;                  // 768/64
    for (int i = 0; i < NCHUNK; i++) {
        int p = i & 1;
        if (i + 1 < NCHUNK) {
            load_chunk(i + 1, p ^ 1);
            cp_wait<1>();
        } else {
            cp_wait<0>();
        }
        __syncthreads();
#pragma unroll
        for (int kk = 0; kk < 64; kk += 16) {
            wmma::fragment<wmma::matrix_a, 16, 16, 16, __half, wmma::row_major> af[4];
            wmma::fragment<wmma::matrix_b, 16, 16, 16, __half, wmma::col_major> bf[2];
#pragma unroll
            for (int q = 0; q < 4; q++)
                wmma::load_matrix_sync(af[q], &Abuf[p][(wy * 64 + q * 16) * LDS_PAD + kk],
                                       LDS_PAD);
#pragma unroll
            for (int q = 0; q < 2; q++)
                wmma::load_matrix_sync(bf[q], &Bbuf[p][(wx * 32 + q * 16) * LDS_PAD + kk],
                                       LDS_PAD);
#pragma unroll
            for (int q = 0; q < 4; q++)
#pragma unroll
                for (int r = 0; r < 2; r++)
                    wmma::mma_sync(acc[q][r], af[q], bf[r], acc[q][r]);
        }
        __syncthreads();
    }

    // epilogue: direct fragment stores (16x16 tiles never cross head/which/batch)
#pragma unroll
    for (int i = 0; i < 4; i++) {
        int row0 = m0 + wy * 64 + i * 16;
#pragma unroll
        for (int j = 0; j < 2; j++) {
            int col0 = n0 + wx * 32 + j * 16;
            if (MODE == 0) {
                int b = row0 >> 10, n = row0 & 1023;
                int which = col0 / 768;
                int c = col0 - which * 768;
                int h = c >> 6, d0 = c & 63;
                float* dst = (which == 0 ? g_Q : (which == 1 ? g_K : g_V))
                             + ((size_t)(b * NHEAD + h) << 16) + (n << 6) + d0;
                wmma::store_matrix_sync(dst, acc[i][j], 64, wmma::mem_row_major);
            } else {
                wmma::store_matrix_sync(outp + (size_t)row0 * 768 + col0, acc[i][j],
                                        768, wmma::mem_row_major);
            }
        }
    }
}

// ============================================================
// per-token learned LR: eta = sigmoid(x·w_h + b_h)/64
// ============================================================
__global__ __launch_bounds__(384) void lr_kernel(
    const float* __restrict__ x, const float* __restrict__ lrw,
    const float* __restrict__ lrb)
{
    int row = blockIdx.x;
    __shared__ float xs[CDIM];
    int t = threadIdx.x;
    for (int i = t; i < CDIM; i += 384) xs[i] = x[(size_t)row * CDIM + i];
    __syncthreads();
    int h = t >> 5, l = t & 31;
    float s = 0.f;
    for (int c = l; c < CDIM; c += 32) s += xs[c] * lrw[h * CDIM + c];
    s = warp_sum(s);
    if (l == 0) {
        float v = 1.f / (1.f + expf(-(s + lrb[h])));
        int b = row >> 10, n = row & 1023;
        g_eta[(b * NHEAD + h) * 1024 + n] = v * (1.f / 64.f);
    }
}

// ============================================================
// TTT phase 1: Z1 = XK@W1+b1; g = ln_fused_l2_bwd * eta/m; b1n
// ============================================================
__global__ __launch_bounds__(256) void ttt_phase1(
    const float* __restrict__ W1, const float* __restrict__ b1,
    const float* __restrict__ gamma, const float* __restrict__ beta)
{
    int bh = blockIdx.x;
    int h = bh % NHEAD;
    __shared__ float W1s[4096];
    __shared__ float b1s[64], gs[64], bs[64];
    __shared__ float gbacc[8 * 64];
    int t = threadIdx.x;
    for (int i = t; i < 4096; i += 256) W1s[i] = W1[h * 4096 + i];
    if (t < 64) {
        b1s[t] = b1[h * 64 + t];
        gs[t]  = gamma[h * 64 + t];
        bs[t]  = beta[h * 64 + t];
    }
    __syncthreads();

    int w = t >> 5, l = t & 31;
    const float* Kp = g_K + (size_t)bh * TOKHD;
    const float* Vp = g_V + (size_t)bh * TOKHD;
    float* Gp = g_G + (size_t)bh * TOKHD;
    const float* etap = g_eta + bh * 1024;

    float gb0 = 0.f, gb1 = 0.f;
    for (int r = w; r < 1024; r += 8) {
        float xk0 = Kp[r * 64 + l], xk1 = Kp[r * 64 + l + 32];
        float z0 = b1s[l], z1 = b1s[l + 32];
#pragma unroll
        for (int c = 0; c < 64; c++) {
            float xc = __shfl_sync(0xffffffffu, (c < 32) ? xk0 : xk1, c & 31);
            z0 = fmaf(xc, W1s[c * 64 + l], z0);
            z1 = fmaf(xc, W1s[c * 64 + l + 32], z1);
        }
        float mu = warp_sum(z0 + z1) * (1.f / 64.f);
        float d0 = z0 - mu, d1 = z1 - mu;
        float var = warp_sum(d0 * d0 + d1 * d1) * (1.f / 64.f);
        float rstd = rsqrtf(var + 1e-6f);
        float xh0 = d0 * rstd, xh1 = d1 * rstd;
        float xv0 = Vp[r * 64 + l], xv1 = Vp[r * 64 + l + 32];
        float go0 = gs[l] * xh0 + bs[l] - (xv0 - xk0);
        float go1 = gs[l + 32] * xh1 + bs[l + 32] - (xv1 - xk1);
        float gg0 = go0 * gs[l], gg1 = go1 * gs[l + 32];
        float sg  = warp_sum(gg0 + gg1);
        float sgx = warp_sum(gg0 * xh0 + gg1 * xh1);
        float sc  = etap[r] * rstd * (1.f / 64.f) * (1.f / 1024.f);
        float gf0 = (64.f * gg0 - sg - xh0 * sgx) * sc;
        float gf1 = (64.f * gg1 - sg - xh1 * sgx) * sc;
        Gp[r * 64 + l] = gf0;
        Gp[r * 64 + l + 32] = gf1;
        gb0 += gf0; gb1 += gf1;
    }
    gbacc[w * 64 + l] = gb0;
    gbacc[w * 64 + l + 32] = gb1;
    __syncthreads();
    if (t < 64) {
        float s = 0.f;
#pragma unroll
        for (int ww = 0; ww < 8; ww++) s += gbacc[ww * 64 + t];
        g_b1n[bh * 64 + t] = b1s[t] - s;
    }
}

// ============================================================
// W1n = W1 - XK^T @ g  (64x64, K=1024)
// ============================================================
__global__ __launch_bounds__(256) void ttt_gradw(const float* __restrict__ W1)
{
    int bh = blockIdx.x;
    int h = bh % NHEAD;
    __shared__ float Ks[32][68];
    __shared__ float Gs[32][68];
    int t = threadIdx.x;
    int tx = t & 15, ty = t >> 4;
    int lr = t >> 3, lc = (t & 7) * 8;
    float acc[4][4];
#pragma unroll
    for (int i = 0; i < 4; i++)
#pragma unroll
        for (int j = 0; j < 4; j++) acc[i][j] = 0.f;

    const float* Kp = g_K + (size_t)bh * TOKHD;
    const float* Gp = g_G + (size_t)bh * TOKHD;

    for (int k0 = 0; k0 < 1024; k0 += 32) {
        float4 kv0 = *(const float4*)(Kp + (k0 + lr) * 64 + lc);
        float4 kv1 = *(const float4*)(Kp + (k0 + lr) * 64 + lc + 4);
        float4 gv0 = *(const float4*)(Gp + (k0 + lr) * 64 + lc);
        float4 gv1 = *(const float4*)(Gp + (k0 + lr) * 64 + lc + 4);
        __syncthreads();
        *(float4*)&Ks[lr][lc]     = kv0;
        *(float4*)&Ks[lr][lc + 4] = kv1;
        *(float4*)&Gs[lr][lc]     = gv0;
        *(float4*)&Gs[lr][lc + 4] = gv1;
        __syncthreads();
#pragma unroll
        for (int r = 0; r < 32; r++) {
            float4 a = *(const float4*)&Ks[r][ty * 4];
            float4 b = *(const float4*)&Gs[r][tx * 4];
            float af[4] = {a.x, a.y, a.z, a.w};
            float bf[4] = {b.x, b.y, b.z, b.w};
#pragma unroll
            for (int i = 0; i < 4; i++)
#pragma unroll
                for (int j = 0; j < 4; j++)
                    acc[i][j] = fmaf(af[i], bf[j], acc[i][j]);
        }
    }
#pragma unroll
    for (int i = 0; i < 4; i++)
#pragma unroll
        for (int j = 0; j < 4; j++) {
            int d = ty * 4 + i, e = tx * 4 + j;
            g_W1n[bh * 4096 + d * 64 + e] = W1[h * 4096 + d * 64 + e] - acc[i][j];
        }
}

// ============================================================
// phase3: out = XQ + ln_fwd(XQ@W1n + b1n) -> g_XQWh (half, [B,N,C])
// ============================================================
__global__ __launch_bounds__(256) void ttt_phase3(
    const float* __restrict__ gamma, const float* __restrict__ beta)
{
    int bh = blockIdx.x;
    int h = bh % NHEAD, b = bh / NHEAD;
    __shared__ float W1s[4096];
    __shared__ float b1s[64], gs[64], bs[64];
    int t = threadIdx.x;
    for (int i = t; i < 4096; i += 256) W1s[i] = g_W1n[bh * 4096 + i];
    if (t < 64) {
        b1s[t] = g_b1n[bh * 64 + t];
        gs[t]  = gamma[h * 64 + t];
        bs[t]  = beta[h * 64 + t];
    }
    __syncthreads();

    int w = t >> 5, l = t & 31;
    const float* Qp = g_Q + (size_t)bh * TOKHD;
    __half* Op = g_XQWh + (size_t)b * 1024 * CDIM;

    for (int r = w; r < 1024; r += 8) {
        float xq0 = Qp[r * 64 + l], xq1 = Qp[r * 64 + l + 32];
        float z0 = b1s[l], z1 = b1s[l + 32];
#pragma unroll
        for (int c = 0; c < 64; c++) {
            float xc = __shfl_sync(0xffffffffu, (c < 32) ? xq0 : xq1, c & 31);
            z0 = fmaf(xc, W1s[c * 64 + l], z0);
            z1 = fmaf(xc, W1s[c * 64 + l + 32], z1);
        }
        float mu = warp_sum(z0 + z1) * (1.f / 64.f);
        float d0 = z0 - mu, d1 = z1 - mu;
        float var = warp_sum(d0 * d0 + d1 * d1) * (1.f / 64.f);
        float rstd = rsqrtf(var + 1e-6f);
        float y0 = gs[l] * (d0 * rstd) + bs[l];
        float y1 = gs[l + 32] * (d1 * rstd) + bs[l + 32];
        Op[r * CDIM + h * 64 + l]      = __float2half(xq0 + y0);
        Op[r * CDIM + h * 64 + l + 32] = __float2half(xq1 + y1);
    }
}

// ============================================================
extern "C" void kernel_launch(void* const* d_in, const int* in_sizes, int n_in,
                              void* d_out, int out_size)
{
    (void)in_sizes; (void)n_in; (void)out_size;
    const float* x     = (const float*)d_in[0];
    const float* qkvw  = (const float*)d_in[1];
    const float* qb    = (const float*)d_in[2];
    const float* vb    = (const float*)d_in[3];
    const float* pw    = (const float*)d_in[4];
    const float* pb    = (const float*)d_in[5];
    const float* lrw   = (const float*)d_in[6];
    const float* lrb   = (const float*)d_in[7];
    const float* gamma = (const float*)d_in[8];
    const float* beta  = (const float*)d_in[9];
    const float* W1    = (const float*)d_in[10];
    const float* b1    = (const float*)d_in[11];
    float* out = (float*)d_out;

    cudaFuncSetAttribute(gemm_fp16<0>, cudaFuncAttributeMaxDynamicSharedMemorySize, GEMM_SMEM);
    cudaFuncSetAttribute(gemm_fp16<1>, cudaFuncAttributeMaxDynamicSharedMemorySize, GEMM_SMEM);

    __half *Xh, *Wqh, *Wph, *XQWh;
    cudaGetSymbolAddress((void**)&Xh, g_Xh);
    cudaGetSymbolAddress((void**)&Wqh, g_Wqh);
    cudaGetSymbolAddress((void**)&Wph, g_Wph);
    cudaGetSymbolAddress((void**)&XQWh, g_XQWh);

    f2h_pass<<<(6291456 + 255) / 256, 256>>>(x, Xh, 6291456);
    f2h_pass<<<(884736 + 255) / 256, 256>>>(qkvw, Wqh, 884736);
    f2h_pass<<<(294912 + 255) / 256, 256>>>(pw, Wph, 294912);

    gemm_fp16<0><<<dim3(18, 128), 256, GEMM_SMEM>>>(Xh, Wqh, qb, vb, nullptr);
    lr_kernel<<<16384, 384>>>(x, lrw, lrb);
    ttt_phase1<<<192, 256>>>(W1, b1, gamma, beta);
    ttt_gradw<<<192, 256>>>(W1);
    ttt_phase3<<<192, 256>>>(gamma, beta);
    gemm_fp16<1><<<dim3(6, 128), 256, GEMM_SMEM>>>(XQWh, Wph, pb, nullptr, out);
}

// round 5
// speedup vs baseline: 3.5778x; 1.5141x over previous
#include <cuda_runtime.h>
#include <cuda_fp16.h>
#include <mma.h>
#include <math.h>
#include <stdint.h>

using namespace nvcuda;

// Problem constants: B=16, N=1024, C=768, H=12, HD=64, one mini-batch (m=1024)
#define NTOK   16384
#define CDIM   768
#define NHEAD  12
#define HD     64
#define BH     192
#define TOKHD  65536          // 1024*64 per (b,h)

// ---- scratch (static device globals; no allocations anywhere) ----
__device__ float  g_Q[12582912];     // [B,H,N,HD] fp32
__device__ float  g_K[12582912];
__device__ float  g_V[12582912];
__device__ float  g_eta[196608];     // [B,H,N]
__device__ float  g_b1n[12288];      // [BH,64]
__device__ __half g_Xh[12582912];    // half(x) [16384,768]
__device__ __half g_Wqh[1769472];    // half(qkv_weight) [2304,768]
__device__ __half g_Wph[589824];     // half(proj_weight) [768,768]
__device__ __half g_XQWh[12582912];  // half pre-projection [B,N,C]
__device__ __half g_Qh[12582912];    // half copies for wmma
__device__ __half g_Kh[12582912];
__device__ __half g_Gh[12582912];    // half g scaled by 1024
__device__ __half g_W1nh[786432];    // half W1n [BH,64,64]

__device__ __forceinline__ float warp_sum(float v) {
#pragma unroll
    for (int o = 16; o > 0; o >>= 1) v += __shfl_xor_sync(0xffffffffu, v, o);
    return v;
}
__device__ __forceinline__ uint32_t smem_u32(const void* p) {
    uint32_t a;
    asm("{ .reg .u64 t; cvta.to.shared.u64 t, %1; cvt.u32.u64 %0, t; }"
        : "=r"(a) : "l"(p));
    return a;
}
__device__ __forceinline__ void cp16(uint32_t dst, const void* src) {
    asm volatile("cp.async.cg.shared.global [%0], [%1], 16;" :: "r"(dst), "l"(src));
}
__device__ __forceinline__ void cp_commit() {
    asm volatile("cp.async.commit_group;" ::: "memory");
}
template <int N> __device__ __forceinline__ void cp_wait() {
    asm volatile("cp.async.wait_group %0;" :: "n"(N) : "memory");
}

// ============================================================
// fp32 -> fp16 conversion pass (half2 stores)
// ============================================================
__global__ void f2h_pass(const float* __restrict__ in, __half* __restrict__ out, int n2)
{
    int i = blockIdx.x * blockDim.x + threadIdx.x;
    if (i < n2) {
        float2 v = ((const float2*)in)[i];
        ((__half2*)out)[i] = __floats2half2_rn(v.x, v.y);
    }
}

// ============================================================
// fp16 wmma GEMM (unchanged from round 4): C = A[M,768] @ W[N,768]^T (+bias)
// ============================================================
#define LDS_PAD 72
#define CHUNK_HALFS (128 * LDS_PAD)
#define GEMM_SMEM (4 * CHUNK_HALFS * 2)

template <int MODE>
__global__ __launch_bounds__(256) void gemm_fp16(
    const __half* __restrict__ A, const __half* __restrict__ Bw,
    const float* __restrict__ bias0, const float* __restrict__ bias1,
    float* __restrict__ outp)
{
    extern __shared__ __half hsm[];
    __half* Abuf[2] = {hsm, hsm + CHUNK_HALFS};
    __half* Bbuf[2] = {hsm + 2 * CHUNK_HALFS, hsm + 3 * CHUNK_HALFS};
    __shared__ float bias2d[16][132];

    int t = threadIdx.x;
    int w = t >> 5;
    int wy = w >> 2, wx = w & 3;
    int m0 = blockIdx.y * 128, n0 = blockIdx.x * 128;

    if (t < 128) {
        int col = n0 + t;
        float bv;
        if (MODE == 0) {
            int which = col / 768, c = col - which * 768;
            bv = (which == 0) ? bias0[c] : ((which == 2) ? bias1[c] : 0.f);
        } else bv = bias0[col];
#pragma unroll
        for (int r = 0; r < 16; r++) bias2d[r][t] = bv;
    }
    __syncthreads();

    wmma::fragment<wmma::accumulator, 16, 16, 16, float> acc[4][2];
#pragma unroll
    for (int i = 0; i < 4; i++)
#pragma unroll
        for (int j = 0; j < 2; j++)
            wmma::load_matrix_sync(acc[i][j], &bias2d[0][wx * 32 + j * 16], 132,
                                   wmma::mem_row_major);

    const __half* gA = A + (size_t)m0 * 768;
    const __half* gB = Bw + (size_t)n0 * 768;
    uint32_t aS[2] = {smem_u32(Abuf[0]), smem_u32(Abuf[1])};
    uint32_t bS[2] = {smem_u32(Bbuf[0]), smem_u32(Bbuf[1])};

    auto load_chunk = [&](int kc, int p) {
#pragma unroll
        for (int j = 0; j < 4; j++) {
            int s = t + j * 256;
            int row = s >> 3, c8 = s & 7;
            cp16(aS[p] + row * (LDS_PAD * 2) + c8 * 16,
                 gA + (size_t)row * 768 + kc * 64 + c8 * 8);
            cp16(bS[p] + row * (LDS_PAD * 2) + c8 * 16,
                 gB + (size_t)row * 768 + kc * 64 + c8 * 8);
        }
        cp_commit();
    };

    load_chunk(0, 0);
    const int NCHUNK = 12;
    for (int i = 0; i < NCHUNK; i++) {
        int p = i & 1;
        if (i + 1 < NCHUNK) { load_chunk(i + 1, p ^ 1); cp_wait<1>(); }
        else cp_wait<0>();
        __syncthreads();
#pragma unroll
        for (int kk = 0; kk < 64; kk += 16) {
            wmma::fragment<wmma::matrix_a, 16, 16, 16, __half, wmma::row_major> af[4];
            wmma::fragment<wmma::matrix_b, 16, 16, 16, __half, wmma::col_major> bf[2];
#pragma unroll
            for (int q = 0; q < 4; q++)
                wmma::load_matrix_sync(af[q], &Abuf[p][(wy * 64 + q * 16) * LDS_PAD + kk],
                                       LDS_PAD);
#pragma unroll
            for (int q = 0; q < 2; q++)
                wmma::load_matrix_sync(bf[q], &Bbuf[p][(wx * 32 + q * 16) * LDS_PAD + kk],
                                       LDS_PAD);
#pragma unroll
            for (int q = 0; q < 4; q++)
#pragma unroll
                for (int r = 0; r < 2; r++)
                    wmma::mma_sync(acc[q][r], af[q], bf[r], acc[q][r]);
        }
        __syncthreads();
    }

#pragma unroll
    for (int i = 0; i < 4; i++) {
        int row0 = m0 + wy * 64 + i * 16;
#pragma unroll
        for (int j = 0; j < 2; j++) {
            int col0 = n0 + wx * 32 + j * 16;
            if (MODE == 0) {
                int b = row0 >> 10, n = row0 & 1023;
                int which = col0 / 768;
                int c = col0 - which * 768;
                int h = c >> 6, d0 = c & 63;
                float* dst = (which == 0 ? g_Q : (which == 1 ? g_K : g_V))
                             + ((size_t)(b * NHEAD + h) << 16) + (n << 6) + d0;
                wmma::store_matrix_sync(dst, acc[i][j], 64, wmma::mem_row_major);
            } else {
                wmma::store_matrix_sync(outp + (size_t)row0 * 768 + col0, acc[i][j],
                                        768, wmma::mem_row_major);
            }
        }
    }
}

// ============================================================
// per-token learned LR: eta = sigmoid(x·w_h + b_h)/64
// ============================================================
__global__ __launch_bounds__(384) void lr_kernel(
    const float* __restrict__ x, const float* __restrict__ lrw,
    const float* __restrict__ lrb)
{
    int row = blockIdx.x;
    __shared__ float xs[CDIM];
    int t = threadIdx.x;
    for (int i = t; i < CDIM; i += 384) xs[i] = x[(size_t)row * CDIM + i];
    __syncthreads();
    int h = t >> 5, l = t & 31;
    float s = 0.f;
    for (int c = l; c < CDIM; c += 32) s += xs[c] * lrw[h * CDIM + c];
    s = warp_sum(s);
    if (l == 0) {
        float v = 1.f / (1.f + expf(-(s + lrb[h])));
        int b = row >> 10, n = row & 1023;
        g_eta[(b * NHEAD + h) * 1024 + n] = v * (1.f / 64.f);
    }
}

// ============================================================
// phase1 (tensor cores): Z1 = XK_h @ W1_h + b1 (wmma -> smem),
// fp32 LN-L2-bwd per row, g stored as half * 1024 in g_Gh,
// b1n = b1 - sum(g) in fp32.
// 8 warps; warp w handles 16-row strips (s*8+w)*16.
// ============================================================
__global__ __launch_bounds__(256) void ttt_phase1_tc(
    const float* __restrict__ W1, const float* __restrict__ b1,
    const float* __restrict__ gamma, const float* __restrict__ beta)
{
    int bh = blockIdx.x;
    int h = bh % NHEAD;
    __shared__ __half W1h[64 * 72];
    __shared__ float zs[8][16 * 68];
    __shared__ float b1s[64], gs[64], bs[64];
    __shared__ float gbacc[8 * 64];
    int t = threadIdx.x, w = t >> 5, l = t & 31;

    for (int i = t; i < 4096; i += 256) {
        int r = i >> 6, c = i & 63;
        W1h[r * 72 + c] = __float2half(W1[h * 4096 + i]);
    }
    if (t < 64) {
        b1s[t] = b1[h * 64 + t];
        gs[t]  = gamma[h * 64 + t];
        bs[t]  = beta[h * 64 + t];
    }
    __syncthreads();

    const __half* Kh = g_Kh + (size_t)bh * TOKHD;
    const float* Kp = g_K + (size_t)bh * TOKHD;
    const float* Vp = g_V + (size_t)bh * TOKHD;
    __half* Gh = g_Gh + (size_t)bh * TOKHD;
    const float* etap = g_eta + bh * 1024;

    float gb0 = 0.f, gb1 = 0.f;
    for (int s = 0; s < 8; s++) {
        int row0 = (s * 8 + w) * 16;
        wmma::fragment<wmma::accumulator, 16, 16, 16, float> acc[4];
#pragma unroll
        for (int n = 0; n < 4; n++) wmma::fill_fragment(acc[n], 0.f);
#pragma unroll
        for (int k = 0; k < 4; k++) {
            wmma::fragment<wmma::matrix_a, 16, 16, 16, __half, wmma::row_major> af;
            wmma::load_matrix_sync(af, Kh + (size_t)row0 * 64 + k * 16, 64);
#pragma unroll
            for (int n = 0; n < 4; n++) {
                wmma::fragment<wmma::matrix_b, 16, 16, 16, __half, wmma::row_major> bf;
                wmma::load_matrix_sync(bf, &W1h[(k * 16) * 72 + n * 16], 72);
                wmma::mma_sync(acc[n], af, bf, acc[n]);
            }
        }
#pragma unroll
        for (int n = 0; n < 4; n++)
            wmma::store_matrix_sync(&zs[w][n * 16], acc[n], 68, wmma::mem_row_major);
        __syncwarp();

#pragma unroll
        for (int r = 0; r < 16; r++) {
            int row = row0 + r;
            float z0 = zs[w][r * 68 + l] + b1s[l];
            float z1 = zs[w][r * 68 + l + 32] + b1s[l + 32];
            float mu = warp_sum(z0 + z1) * (1.f / 64.f);
            float d0 = z0 - mu, d1 = z1 - mu;
            float var = warp_sum(d0 * d0 + d1 * d1) * (1.f / 64.f);
            float rstd = rsqrtf(var + 1e-6f);
            float xh0 = d0 * rstd, xh1 = d1 * rstd;
            float xk0 = Kp[row * 64 + l], xk1 = Kp[row * 64 + l + 32];
            float xv0 = Vp[row * 64 + l], xv1 = Vp[row * 64 + l + 32];
            float go0 = gs[l] * xh0 + bs[l] - (xv0 - xk0);
            float go1 = gs[l + 32] * xh1 + bs[l + 32] - (xv1 - xk1);
            float gg0 = go0 * gs[l], gg1 = go1 * gs[l + 32];
            float sg  = warp_sum(gg0 + gg1);
            float sgx = warp_sum(gg0 * xh0 + gg1 * xh1);
            float sc  = etap[row] * rstd * (1.f / 64.f) * (1.f / 1024.f);
            float gf0 = (64.f * gg0 - sg - xh0 * sgx) * sc;
            float gf1 = (64.f * gg1 - sg - xh1 * sgx) * sc;
            // store g * 1024 as half (defers /m; avoids fp16 underflow)
            Gh[row * 64 + l]      = __float2half(gf0 * 1024.f);
            Gh[row * 64 + l + 32] = __float2half(gf1 * 1024.f);
            gb0 += gf0; gb1 += gf1;
        }
    }
    gbacc[w * 64 + l] = gb0;
    gbacc[w * 64 + l + 32] = gb1;
    __syncthreads();
    if (t < 64) {
        float s = 0.f;
#pragma unroll
        for (int ww = 0; ww < 8; ww++) s += gbacc[ww * 64 + t];
        g_b1n[bh * 64 + t] = b1s[t] - s;
    }
}

// ============================================================
// gradw (tensor cores): W1n = W1 - (XK_h^T @ g_h)/1024, output half.
// 8 warps = 4 output row-tiles (16x64) x 2 K-halves; smem pairwise reduce.
// ============================================================
__global__ __launch_bounds__(256) void ttt_gradw_tc(const float* __restrict__ W1)
{
    int bh = blockIdx.x;
    int h = bh % NHEAD;
    __shared__ float parts[8][16 * 68];
    int t = threadIdx.x, w = t >> 5;
    int wt = w & 3, kh = w >> 2;

    const __half* Kh = g_Kh + (size_t)bh * TOKHD;
    const __half* Gh = g_Gh + (size_t)bh * TOKHD;

    wmma::fragment<wmma::accumulator, 16, 16, 16, float> acc[4];
#pragma unroll
    for (int n = 0; n < 4; n++) wmma::fill_fragment(acc[n], 0.f);

    for (int ks = 0; ks < 32; ks++) {
        int k = kh * 512 + ks * 16;
        wmma::fragment<wmma::matrix_a, 16, 16, 16, __half, wmma::col_major> af;
        wmma::load_matrix_sync(af, Kh + (size_t)k * 64 + wt * 16, 64);
#pragma unroll
        for (int n = 0; n < 4; n++) {
            wmma::fragment<wmma::matrix_b, 16, 16, 16, __half, wmma::row_major> bf;
            wmma::load_matrix_sync(bf, Gh + (size_t)k * 64 + n * 16, 64);
            wmma::mma_sync(acc[n], af, bf, acc[n]);
        }
    }
#pragma unroll
    for (int n = 0; n < 4; n++)
        wmma::store_matrix_sync(&parts[w][n * 16], acc[n], 68, wmma::mem_row_major);
    __syncthreads();

    for (int i = t; i < 4096; i += 256) {
        int d = i >> 6, e = i & 63;
        int wt2 = d >> 4, r = d & 15;
        float gsum = parts[wt2][r * 68 + e] + parts[wt2 + 4][r * 68 + e];
        g_W1nh[(size_t)bh * 4096 + i] =
            __float2half(W1[h * 4096 + i] - gsum * (1.f / 1024.f));
    }
}

// ============================================================
// phase3 (tensor cores): Z = XQ_h @ W1n_h + b1n (wmma -> smem),
// fp32 LN fwd, out = XQ_f32 + y -> g_XQWh (half, [B,N,C]).
// ============================================================
__global__ __launch_bounds__(256) void ttt_phase3_tc(
    const float* __restrict__ gamma, const float* __restrict__ beta)
{
    int bh = blockIdx.x;
    int h = bh % NHEAD, b = bh / NHEAD;
    __shared__ __half W1h[64 * 72];
    __shared__ float zs[8][16 * 68];
    __shared__ float b1s[64], gs[64], bs[64];
    int t = threadIdx.x, w = t >> 5, l = t & 31;

    for (int i = t; i < 4096; i += 256) {
        int r = i >> 6, c = i & 63;
        W1h[r * 72 + c] = g_W1nh[(size_t)bh * 4096 + i];
    }
    if (t < 64) {
        b1s[t] = g_b1n[bh * 64 + t];
        gs[t]  = gamma[h * 64 + t];
        bs[t]  = beta[h * 64 + t];
    }
    __syncthreads();

    const __half* Qh = g_Qh + (size_t)bh * TOKHD;
    const float* Qp = g_Q + (size_t)bh * TOKHD;
    __half* Op = g_XQWh + (size_t)b * 1024 * CDIM;

    for (int s = 0; s < 8; s++) {
        int row0 = (s * 8 + w) * 16;
        wmma::fragment<wmma::accumulator, 16, 16, 16, float> acc[4];
#pragma unroll
        for (int n = 0; n < 4; n++) wmma::fill_fragment(acc[n], 0.f);
#pragma unroll
        for (int k = 0; k < 4; k++) {
            wmma::fragment<wmma::matrix_a, 16, 16, 16, __half, wmma::row_major> af;
            wmma::load_matrix_sync(af, Qh + (size_t)row0 * 64 + k * 16, 64);
#pragma unroll
            for (int n = 0; n < 4; n++) {
                wmma::fragment<wmma::matrix_b, 16, 16, 16, __half, wmma::row_major> bf;
                wmma::load_matrix_sync(bf, &W1h[(k * 16) * 72 + n * 16], 72);
                wmma::mma_sync(acc[n], af, bf, acc[n]);
            }
        }
#pragma unroll
        for (int n = 0; n < 4; n++)
            wmma::store_matrix_sync(&zs[w][n * 16], acc[n], 68, wmma::mem_row_major);
        __syncwarp();

#pragma unroll
        for (int r = 0; r < 16; r++) {
            int row = row0 + r;
            float z0 = zs[w][r * 68 + l] + b1s[l];
            float z1 = zs[w][r * 68 + l + 32] + b1s[l + 32];
            float mu = warp_sum(z0 + z1) * (1.f / 64.f);
            float d0 = z0 - mu, d1 = z1 - mu;
            float var = warp_sum(d0 * d0 + d1 * d1) * (1.f / 64.f);
            float rstd = rsqrtf(var + 1e-6f);
            float y0 = gs[l] * (d0 * rstd) + bs[l];
            float y1 = gs[l + 32] * (d1 * rstd) + bs[l + 32];
            float xq0 = Qp[row * 64 + l], xq1 = Qp[row * 64 + l + 32];
            Op[row * CDIM + h * 64 + l]      = __float2half(xq0 + y0);
            Op[row * CDIM + h * 64 + l + 32] = __float2half(xq1 + y1);
        }
    }
}

// ============================================================
extern "C" void kernel_launch(void* const* d_in, const int* in_sizes, int n_in,
                              void* d_out, int out_size)
{
    (void)in_sizes; (void)n_in; (void)out_size;
    const float* x     = (const float*)d_in[0];
    const float* qkvw  = (const float*)d_in[1];
    const float* qb    = (const float*)d_in[2];
    const float* vb    = (const float*)d_in[3];
    const float* pw    = (const float*)d_in[4];
    const float* pb    = (const float*)d_in[5];
    const float* lrw   = (const float*)d_in[6];
    const float* lrb   = (const float*)d_in[7];
    const float* gamma = (const float*)d_in[8];
    const float* beta  = (const float*)d_in[9];
    const float* W1    = (const float*)d_in[10];
    const float* b1    = (const float*)d_in[11];
    float* out = (float*)d_out;

    cudaFuncSetAttribute(gemm_fp16<0>, cudaFuncAttributeMaxDynamicSharedMemorySize, GEMM_SMEM);
    cudaFuncSetAttribute(gemm_fp16<1>, cudaFuncAttributeMaxDynamicSharedMemorySize, GEMM_SMEM);

    __half *Xh, *Wqh, *Wph, *XQWh, *Qh, *Kh;
    float *Qf, *Kf;
    cudaGetSymbolAddress((void**)&Xh, g_Xh);
    cudaGetSymbolAddress((void**)&Wqh, g_Wqh);
    cudaGetSymbolAddress((void**)&Wph, g_Wph);
    cudaGetSymbolAddress((void**)&XQWh, g_XQWh);
    cudaGetSymbolAddress((void**)&Qh, g_Qh);
    cudaGetSymbolAddress((void**)&Kh, g_Kh);
    cudaGetSymbolAddress((void**)&Qf, g_Q);
    cudaGetSymbolAddress((void**)&Kf, g_K);

    f2h_pass<<<(6291456 + 255) / 256, 256>>>(x, Xh, 6291456);
    f2h_pass<<<(884736 + 255) / 256, 256>>>(qkvw, Wqh, 884736);
    f2h_pass<<<(294912 + 255) / 256, 256>>>(pw, Wph, 294912);

    gemm_fp16<0><<<dim3(18, 128), 256, GEMM_SMEM>>>(Xh, Wqh, qb, vb, nullptr);

    f2h_pass<<<(6291456 + 255) / 256, 256>>>(Qf, Qh, 6291456);
    f2h_pass<<<(6291456 + 255) / 256, 256>>>(Kf, Kh, 6291456);
    lr_kernel<<<16384, 384>>>(x, lrw, lrb);

    ttt_phase1_tc<<<192, 256>>>(W1, b1, gamma, beta);
    ttt_gradw_tc<<<192, 256>>>(W1);
    ttt_phase3_tc<<<192, 256>>>(gamma, beta);

    gemm_fp16<1><<<dim3(6, 128), 256, GEMM_SMEM>>>(XQWh, Wph, pb, nullptr, out);
}

// round 6
// speedup vs baseline: 3.6774x; 1.0278x over previous
#include <cuda_runtime.h>
#include <cuda_fp16.h>
#include <mma.h>
#include <math.h>
#include <stdint.h>

using namespace nvcuda;

// Problem constants: B=16, N=1024, C=768, H=12, HD=64, one mini-batch (m=1024)
#define NTOK   16384
#define CDIM   768
#define NHEAD  12
#define HD     64
#define BH     192
#define TOKHD  65536          // 1024*64 per (b,h)

// ---- scratch (static device globals; no allocations anywhere) ----
__device__ float  g_Q[12582912];     // [B,H,N,HD] fp32
__device__ float  g_K[12582912];
__device__ float  g_V[12582912];
__device__ float  g_eta[196608];     // [B,H,N]
__device__ float  g_b1n[12288];      // [BH,64]
__device__ __half g_Xh[12582912];    // half(x) [16384,768]
__device__ __half g_Wqh[1769472];    // half(qkv_weight) [2304,768]
__device__ __half g_Wph[589824];     // half(proj_weight) [768,768]
__device__ __half g_XQWh[12582912];  // half pre-projection [B,N,C]
__device__ __half g_Qh[12582912];    // half Q (written by gemm epilogue)
__device__ __half g_Kh[12582912];    // half K (written by gemm epilogue)
__device__ __half g_Gh[12582912];    // half g scaled by 1024
__device__ __half g_W1nh[786432];    // half W1n [BH,64,64]

__device__ __forceinline__ float warp_sum(float v) {
#pragma unroll
    for (int o = 16; o > 0; o >>= 1) v += __shfl_xor_sync(0xffffffffu, v, o);
    return v;
}
__device__ __forceinline__ uint32_t smem_u32(const void* p) {
    uint32_t a;
    asm("{ .reg .u64 t; cvta.to.shared.u64 t, %1; cvt.u32.u64 %0, t; }"
        : "=r"(a) : "l"(p));
    return a;
}
__device__ __forceinline__ void cp16(uint32_t dst, const void* src) {
    asm volatile("cp.async.cg.shared.global [%0], [%1], 16;" :: "r"(dst), "l"(src));
}
__device__ __forceinline__ void cp_commit() {
    asm volatile("cp.async.commit_group;" ::: "memory");
}
template <int N> __device__ __forceinline__ void cp_wait() {
    asm volatile("cp.async.wait_group %0;" :: "n"(N) : "memory");
}

// ============================================================
// fp32 -> fp16 conversion pass (half2 stores)
// ============================================================
__global__ void f2h_pass(const float* __restrict__ in, __half* __restrict__ out, int n2)
{
    int i = blockIdx.x * blockDim.x + threadIdx.x;
    if (i < n2) {
        float2 v = ((const float2*)in)[i];
        ((__half2*)out)[i] = __floats2half2_rn(v.x, v.y);
    }
}

// ============================================================
// fp16 wmma GEMM: C = A[M,768] @ W[N,768]^T (+bias)
// Block tile 128(M) x 256(N), 8 warps, warp tile 64x64 (acc[4][4]).
// 3-stage cp.async pipeline, K chunks of 64.
// MODE 0: scatter into g_Q/g_K/g_V [B,H,N,64] (+bias), and ALSO write
//         half copies g_Qh/g_Kh via smem staging (fused f2h).
// MODE 1: direct store to outp [M,768] (+bias).
// ============================================================
#define LDS_PAD 72
#define A_CH (128 * LDS_PAD)          // halfs per A stage
#define B_CH (256 * LDS_PAD)          // halfs per B stage
#define STAGE_HALFS (A_CH + B_CH)
#define NSTAGE 3
#define GEMM_SMEM (NSTAGE * STAGE_HALFS * 2)   // 165888 bytes

template <int MODE>
__global__ __launch_bounds__(256, 1) void gemm_fp16(
    const __half* __restrict__ A, const __half* __restrict__ Bw,
    const float* __restrict__ bias0, const float* __restrict__ bias1,
    float* __restrict__ outp)
{
    extern __shared__ __half hsm[];
    __shared__ float bias2d[16][264];
    __shared__ float stg[8][16 * 18];

    int t = threadIdx.x;
    int w = t >> 5, lid = t & 31;
    int wy = w >> 2, wx = w & 3;          // warp tile 64(m) x 64(n); 2x4 warps
    int m0 = blockIdx.y * 128, n0 = blockIdx.x * 256;

    {   // bias tile (16 identical rows)
        int col = n0 + t;
        float bv;
        if (MODE == 0) {
            int which = col / 768, c = col - which * 768;
            bv = (which == 0) ? bias0[c] : ((which == 2) ? bias1[c] : 0.f);
        } else bv = bias0[col];
#pragma unroll
        for (int r = 0; r < 16; r++) bias2d[r][t] = bv;
    }
    __syncthreads();

    wmma::fragment<wmma::accumulator, 16, 16, 16, float> acc[4][4];
#pragma unroll
    for (int i = 0; i < 4; i++)
#pragma unroll
        for (int j = 0; j < 4; j++)
            wmma::load_matrix_sync(acc[i][j], &bias2d[0][wx * 64 + j * 16], 264,
                                   wmma::mem_row_major);

    const __half* gA = A + (size_t)m0 * 768;
    const __half* gB = Bw + (size_t)n0 * 768;

    auto stageA = [&](int s) -> __half* { return hsm + s * STAGE_HALFS; };
    auto stageB = [&](int s) -> __half* { return hsm + s * STAGE_HALFS + A_CH; };

    auto load_chunk = [&](int kc, int s) {
        uint32_t aS = smem_u32(stageA(s));
        uint32_t bS = smem_u32(stageB(s));
#pragma unroll
        for (int j = 0; j < 4; j++) {
            int it = t + j * 256;               // 0..1023
            int row = it >> 3, c8 = it & 7;
            cp16(aS + row * (LDS_PAD * 2) + c8 * 16,
                 gA + (size_t)row * 768 + kc * 64 + c8 * 8);
        }
#pragma unroll
        for (int j = 0; j < 8; j++) {
            int it = t + j * 256;               // 0..2047
            int row = it >> 3, c8 = it & 7;
            cp16(bS + row * (LDS_PAD * 2) + c8 * 16,
                 gB + (size_t)row * 768 + kc * 64 + c8 * 8);
        }
        cp_commit();
    };

    const int NCHUNK = 12;                      // 768/64
    load_chunk(0, 0);
    load_chunk(1, 1);
    for (int i = 0; i < NCHUNK; i++) {
        int p = i % NSTAGE;
        if (i + 2 < NCHUNK) { load_chunk(i + 2, (i + 2) % NSTAGE); cp_wait<2>(); }
        else if (i + 1 < NCHUNK) cp_wait<1>();
        else cp_wait<0>();
        __syncthreads();

        __half* As = stageA(p);
        __half* Bs = stageB(p);
#pragma unroll
        for (int kk = 0; kk < 64; kk += 16) {
            wmma::fragment<wmma::matrix_a, 16, 16, 16, __half, wmma::row_major> af[4];
            wmma::fragment<wmma::matrix_b, 16, 16, 16, __half, wmma::col_major> bf[4];
#pragma unroll
            for (int q = 0; q < 4; q++)
                wmma::load_matrix_sync(af[q], &As[(wy * 64 + q * 16) * LDS_PAD + kk],
                                       LDS_PAD);
#pragma unroll
            for (int q = 0; q < 4; q++)
                wmma::load_matrix_sync(bf[q], &Bs[(wx * 64 + q * 16) * LDS_PAD + kk],
                                       LDS_PAD);
#pragma unroll
            for (int q = 0; q < 4; q++)
#pragma unroll
                for (int r = 0; r < 4; r++)
                    wmma::mma_sync(acc[q][r], af[q], bf[r], acc[q][r]);
        }
        __syncthreads();
    }

    // epilogue
#pragma unroll
    for (int i = 0; i < 4; i++) {
        int row0 = m0 + wy * 64 + i * 16;
#pragma unroll
        for (int j = 0; j < 4; j++) {
            int col0 = n0 + wx * 64 + j * 16;
            if (MODE == 0) {
                int b = row0 >> 10, n = row0 & 1023;
                int which = col0 / 768;
                int c = col0 - which * 768;
                int h = c >> 6, d0 = c & 63;
                size_t off = ((size_t)(b * NHEAD + h) << 16) + (n << 6) + d0;
                float* dst = (which == 0 ? g_Q : (which == 1 ? g_K : g_V)) + off;
                wmma::store_matrix_sync(dst, acc[i][j], 64, wmma::mem_row_major);
                if (which <= 1) {
                    // fused half conversion via warp-private staging
                    float* stw = &stg[w][0];
                    wmma::store_matrix_sync(stw, acc[i][j], 18, wmma::mem_row_major);
                    __syncwarp();
                    __half* dsth = (which == 0 ? g_Qh : g_Kh) + off;
                    int rr = lid >> 1, cc = (lid & 1) * 8;
                    float* sp = stw + rr * 18 + cc;
                    __half2 h0 = __floats2half2_rn(sp[0], sp[1]);
                    __half2 h1 = __floats2half2_rn(sp[2], sp[3]);
                    __half2 h2 = __floats2half2_rn(sp[4], sp[5]);
                    __half2 h3 = __floats2half2_rn(sp[6], sp[7]);
                    __half2* dp = (__half2*)(dsth + (size_t)rr * 64 + cc);
                    dp[0] = h0; dp[1] = h1; dp[2] = h2; dp[3] = h3;
                    __syncwarp();
                }
            } else {
                wmma::store_matrix_sync(outp + (size_t)row0 * 768 + col0, acc[i][j],
                                        768, wmma::mem_row_major);
            }
        }
    }
}

// ============================================================
// learned LR: eta = sigmoid(x·w_h + b_h)/64 — smem-cached weights,
// 128 blocks x 8 warps x 16 rows.
// ============================================================
__global__ __launch_bounds__(256) void lr_kernel2(
    const float* __restrict__ x, const float* __restrict__ lrw,
    const float* __restrict__ lrb)
{
    __shared__ float ws[12 * 768];
    __shared__ float lb[12];
    int t = threadIdx.x, w = t >> 5, l = t & 31;
    for (int i = t; i < 12 * 768; i += 256) ws[i] = lrw[i];
    if (t < 12) lb[t] = lrb[t];
    __syncthreads();

    int rowbase = blockIdx.x * 128 + w * 16;
    for (int rr = 0; rr < 16; rr++) {
        int row = rowbase + rr;
        const float* xr = x + (size_t)row * 768;
        float xv[24];
#pragma unroll
        for (int k = 0; k < 24; k++) xv[k] = xr[l + k * 32];
#pragma unroll
        for (int h = 0; h < 12; h++) {
            float s = 0.f;
#pragma unroll
            for (int k = 0; k < 24; k++) s = fmaf(xv[k], ws[h * 768 + l + k * 32], s);
            s = warp_sum(s);
            if (l == 0) {
                float v = 1.f / (1.f + expf(-(s + lb[h])));
                int b = row >> 10, n = row & 1023;
                g_eta[(b * NHEAD + h) * 1024 + n] = v * (1.f / 64.f);
            }
        }
    }
}

// ============================================================
// phase1 (tensor cores): Z1 = XK_h @ W1_h + b1 (wmma -> smem),
// fp32 LN-L2-bwd per row, g stored as half * 1024 in g_Gh,
// b1n = b1 - sum(g) in fp32.
// ============================================================
__global__ __launch_bounds__(256) void ttt_phase1_tc(
    const float* __restrict__ W1, const float* __restrict__ b1,
    const float* __restrict__ gamma, const float* __restrict__ beta)
{
    int bh = blockIdx.x;
    int h = bh % NHEAD;
    __shared__ __half W1h[64 * 72];
    __shared__ float zs[8][16 * 68];
    __shared__ float b1s[64], gs[64], bs[64];
    __shared__ float gbacc[8 * 64];
    int t = threadIdx.x, w = t >> 5, l = t & 31;

    for (int i = t; i < 4096; i += 256) {
        int r = i >> 6, c = i & 63;
        W1h[r * 72 + c] = __float2half(W1[h * 4096 + i]);
    }
    if (t < 64) {
        b1s[t] = b1[h * 64 + t];
        gs[t]  = gamma[h * 64 + t];
        bs[t]  = beta[h * 64 + t];
    }
    __syncthreads();

    const __half* Kh = g_Kh + (size_t)bh * TOKHD;
    const float* Kp = g_K + (size_t)bh * TOKHD;
    const float* Vp = g_V + (size_t)bh * TOKHD;
    __half* Gh = g_Gh + (size_t)bh * TOKHD;
    const float* etap = g_eta + bh * 1024;

    float gb0 = 0.f, gb1 = 0.f;
    for (int s = 0; s < 8; s++) {
        int row0 = (s * 8 + w) * 16;
        wmma::fragment<wmma::accumulator, 16, 16, 16, float> acc[4];
#pragma unroll
        for (int n = 0; n < 4; n++) wmma::fill_fragment(acc[n], 0.f);
#pragma unroll
        for (int k = 0; k < 4; k++) {
            wmma::fragment<wmma::matrix_a, 16, 16, 16, __half, wmma::row_major> af;
            wmma::load_matrix_sync(af, Kh + (size_t)row0 * 64 + k * 16, 64);
#pragma unroll
            for (int n = 0; n < 4; n++) {
                wmma::fragment<wmma::matrix_b, 16, 16, 16, __half, wmma::row_major> bf;
                wmma::load_matrix_sync(bf, &W1h[(k * 16) * 72 + n * 16], 72);
                wmma::mma_sync(acc[n], af, bf, acc[n]);
            }
        }
#pragma unroll
        for (int n = 0; n < 4; n++)
            wmma::store_matrix_sync(&zs[w][n * 16], acc[n], 68, wmma::mem_row_major);
        __syncwarp();

#pragma unroll
        for (int r = 0; r < 16; r++) {
            int row = row0 + r;
            float z0 = zs[w][r * 68 + l] + b1s[l];
            float z1 = zs[w][r * 68 + l + 32] + b1s[l + 32];
            float mu = warp_sum(z0 + z1) * (1.f / 64.f);
            float d0 = z0 - mu, d1 = z1 - mu;
            float var = warp_sum(d0 * d0 + d1 * d1) * (1.f / 64.f);
            float rstd = rsqrtf(var + 1e-6f);
            float xh0 = d0 * rstd, xh1 = d1 * rstd;
            float xk0 = Kp[row * 64 + l], xk1 = Kp[row * 64 + l + 32];
            float xv0 = Vp[row * 64 + l], xv1 = Vp[row * 64 + l + 32];
            float go0 = gs[l] * xh0 + bs[l] - (xv0 - xk0);
            float go1 = gs[l + 32] * xh1 + bs[l + 32] - (xv1 - xk1);
            float gg0 = go0 * gs[l], gg1 = go1 * gs[l + 32];
            float sg  = warp_sum(gg0 + gg1);
            float sgx = warp_sum(gg0 * xh0 + gg1 * xh1);
            float sc  = etap[row] * rstd * (1.f / 64.f) * (1.f / 1024.f);
            float gf0 = (64.f * gg0 - sg - xh0 * sgx) * sc;
            float gf1 = (64.f * gg1 - sg - xh1 * sgx) * sc;
            Gh[row * 64 + l]      = __float2half(gf0 * 1024.f);
            Gh[row * 64 + l + 32] = __float2half(gf1 * 1024.f);
            gb0 += gf0; gb1 += gf1;
        }
    }
    gbacc[w * 64 + l] = gb0;
    gbacc[w * 64 + l + 32] = gb1;
    __syncthreads();
    if (t < 64) {
        float s = 0.f;
#pragma unroll
        for (int ww = 0; ww < 8; ww++) s += gbacc[ww * 64 + t];
        g_b1n[bh * 64 + t] = b1s[t] - s;
    }
}

// ============================================================
// gradw (tensor cores): W1n = W1 - (XK_h^T @ g_h)/1024, output half.
// ============================================================
__global__ __launch_bounds__(256) void ttt_gradw_tc(const float* __restrict__ W1)
{
    int bh = blockIdx.x;
    int h = bh % NHEAD;
    __shared__ float parts[8][16 * 68];
    int t = threadIdx.x, w = t >> 5;
    int wt = w & 3, kh = w >> 2;

    const __half* Kh = g_Kh + (size_t)bh * TOKHD;
    const __half* Gh = g_Gh + (size_t)bh * TOKHD;

    wmma::fragment<wmma::accumulator, 16, 16, 16, float> acc[4];
#pragma unroll
    for (int n = 0; n < 4; n++) wmma::fill_fragment(acc[n], 0.f);

    for (int ks = 0; ks < 32; ks++) {
        int k = kh * 512 + ks * 16;
        wmma::fragment<wmma::matrix_a, 16, 16, 16, __half, wmma::col_major> af;
        wmma::load_matrix_sync(af, Kh + (size_t)k * 64 + wt * 16, 64);
#pragma unroll
        for (int n = 0; n < 4; n++) {
            wmma::fragment<wmma::matrix_b, 16, 16, 16, __half, wmma::row_major> bf;
            wmma::load_matrix_sync(bf, Gh + (size_t)k * 64 + n * 16, 64);
            wmma::mma_sync(acc[n], af, bf, acc[n]);
        }
    }
#pragma unroll
    for (int n = 0; n < 4; n++)
        wmma::store_matrix_sync(&parts[w][n * 16], acc[n], 68, wmma::mem_row_major);
    __syncthreads();

    for (int i = t; i < 4096; i += 256) {
        int d = i >> 6, e = i & 63;
        int wt2 = d >> 4, r = d & 15;
        float gsum = parts[wt2][r * 68 + e] + parts[wt2 + 4][r * 68 + e];
        g_W1nh[(size_t)bh * 4096 + i] =
            __float2half(W1[h * 4096 + i] - gsum * (1.f / 1024.f));
    }
}

// ============================================================
// phase3 (tensor cores): Z = XQ_h @ W1n_h + b1n, fp32 LN fwd,
// out = XQ_f32 + y -> g_XQWh (half, [B,N,C]).
// ============================================================
__global__ __launch_bounds__(256) void ttt_phase3_tc(
    const float* __restrict__ gamma, const float* __restrict__ beta)
{
    int bh = blockIdx.x;
    int h = bh % NHEAD, b = bh / NHEAD;
    __shared__ __half W1h[64 * 72];
    __shared__ float zs[8][16 * 68];
    __shared__ float b1s[64], gs[64], bs[64];
    int t = threadIdx.x, w = t >> 5, l = t & 31;

    for (int i = t; i < 4096; i += 256) {
        int r = i >> 6, c = i & 63;
        W1h[r * 72 + c] = g_W1nh[(size_t)bh * 4096 + i];
    }
    if (t < 64) {
        b1s[t] = g_b1n[bh * 64 + t];
        gs[t]  = gamma[h * 64 + t];
        bs[t]  = beta[h * 64 + t];
    }
    __syncthreads();

    const __half* Qh = g_Qh + (size_t)bh * TOKHD;
    const float* Qp = g_Q + (size_t)bh * TOKHD;
    __half* Op = g_XQWh + (size_t)b * 1024 * CDIM;

    for (int s = 0; s < 8; s++) {
        int row0 = (s * 8 + w) * 16;
        wmma::fragment<wmma::accumulator, 16, 16, 16, float> acc[4];
#pragma unroll
        for (int n = 0; n < 4; n++) wmma::fill_fragment(acc[n], 0.f);
#pragma unroll
        for (int k = 0; k < 4; k++) {
            wmma::fragment<wmma::matrix_a, 16, 16, 16, __half, wmma::row_major> af;
            wmma::load_matrix_sync(af, Qh + (size_t)row0 * 64 + k * 16, 64);
#pragma unroll
            for (int n = 0; n < 4; n++) {
                wmma::fragment<wmma::matrix_b, 16, 16, 16, __half, wmma::row_major> bf;
                wmma::load_matrix_sync(bf, &W1h[(k * 16) * 72 + n * 16], 72);
                wmma::mma_sync(acc[n], af, bf, acc[n]);
            }
        }
#pragma unroll
        for (int n = 0; n < 4; n++)
            wmma::store_matrix_sync(&zs[w][n * 16], acc[n], 68, wmma::mem_row_major);
        __syncwarp();

#pragma unroll
        for (int r = 0; r < 16; r++) {
            int row = row0 + r;
            float z0 = zs[w][r * 68 + l] + b1s[l];
            float z1 = zs[w][r * 68 + l + 32] + b1s[l + 32];
            float mu = warp_sum(z0 + z1) * (1.f / 64.f);
            float d0 = z0 - mu, d1 = z1 - mu;
            float var = warp_sum(d0 * d0 + d1 * d1) * (1.f / 64.f);
            float rstd = rsqrtf(var + 1e-6f);
            float y0 = gs[l] * (d0 * rstd) + bs[l];
            float y1 = gs[l + 32] * (d1 * rstd) + bs[l + 32];
            float xq0 = Qp[row * 64 + l], xq1 = Qp[row * 64 + l + 32];
            Op[row * CDIM + h * 64 + l]      = __float2half(xq0 + y0);
            Op[row * CDIM + h * 64 + l + 32] = __float2half(xq1 + y1);
        }
    }
}

// ============================================================
extern "C" void kernel_launch(void* const* d_in, const int* in_sizes, int n_in,
                              void* d_out, int out_size)
{
    (void)in_sizes; (void)n_in; (void)out_size;
    const float* x     = (const float*)d_in[0];
    const float* qkvw  = (const float*)d_in[1];
    const float* qb    = (const float*)d_in[2];
    const float* vb    = (const float*)d_in[3];
    const float* pw    = (const float*)d_in[4];
    const float* pb    = (const float*)d_in[5];
    const float* lrw   = (const float*)d_in[6];
    const float* lrb   = (const float*)d_in[7];
    const float* gamma = (const float*)d_in[8];
    const float* beta  = (const float*)d_in[9];
    const float* W1    = (const float*)d_in[10];
    const float* b1    = (const float*)d_in[11];
    float* out = (float*)d_out;

    cudaFuncSetAttribute(gemm_fp16<0>, cudaFuncAttributeMaxDynamicSharedMemorySize, GEMM_SMEM);
    cudaFuncSetAttribute(gemm_fp16<1>, cudaFuncAttributeMaxDynamicSharedMemorySize, GEMM_SMEM);

    __half *Xh, *Wqh, *Wph, *XQWh;
    cudaGetSymbolAddress((void**)&Xh, g_Xh);
    cudaGetSymbolAddress((void**)&Wqh, g_Wqh);
    cudaGetSymbolAddress((void**)&Wph, g_Wph);
    cudaGetSymbolAddress((void**)&XQWh, g_XQWh);

    f2h_pass<<<(6291456 + 255) / 256, 256>>>(x, Xh, 6291456);
    f2h_pass<<<(884736 + 255) / 256, 256>>>(qkvw, Wqh, 884736);
    f2h_pass<<<(294912 + 255) / 256, 256>>>(pw, Wph, 294912);

    gemm_fp16<0><<<dim3(9, 128), 256, GEMM_SMEM>>>(Xh, Wqh, qb, vb, nullptr);

    lr_kernel2<<<128, 256>>>(x, lrw, lrb);
    ttt_phase1_tc<<<192, 256>>>(W1, b1, gamma, beta);
    ttt_gradw_tc<<<192, 256>>>(W1);
    ttt_phase3_tc<<<192, 256>>>(gamma, beta);

    gemm_fp16<1><<<dim3(3, 128), 256, GEMM_SMEM>>>(XQWh, Wph, pb, nullptr, out);
}

// round 7
// speedup vs baseline: 4.0585x; 1.1036x over previous
#include <cuda_runtime.h>
#include <cuda_fp16.h>
#include <mma.h>
#include <math.h>
#include <stdint.h>

using namespace nvcuda;

// Problem constants: B=16, N=1024, C=768, H=12, HD=64, one mini-batch (m=1024)
#define NTOK   16384
#define CDIM   768
#define NHEAD  12
#define HD     64
#define BH     192
#define TOKHD  65536          // 1024*64 per (b,h)

// ---- scratch (static device globals; no allocations anywhere) ----
__device__ float  g_Q[12582912];     // [B,H,N,HD] fp32
__device__ float  g_K[12582912];
__device__ float  g_V[12582912];
__device__ float  g_eta[196608];     // [B,H,N]
__device__ float  g_b1n[12288];      // [BH,64]
__device__ float  g_b1part[49152];   // [BH,4,64] partial b1 grad sums
__device__ __half g_Xh[12582912];    // half(x) [16384,768]
__device__ __half g_Wqh[1769472];    // half(qkv_weight) [2304,768]
__device__ __half g_Wph[589824];     // half(proj_weight) [768,768]
__device__ __half g_XQWh[12582912];  // half pre-projection [B,N,C]
__device__ __half g_Qh[12582912];    // half Q (written by gemm epilogue)
__device__ __half g_Kh[12582912];    // half K (written by gemm epilogue)
__device__ __half g_Gh[12582912];    // half g scaled by 1024
__device__ __half g_W1nh[786432];    // half W1n [BH,64,64]

__device__ __forceinline__ float warp_sum(float v) {
#pragma unroll
    for (int o = 16; o > 0; o >>= 1) v += __shfl_xor_sync(0xffffffffu, v, o);
    return v;
}
__device__ __forceinline__ uint32_t smem_u32(const void* p) {
    uint32_t a;
    asm("{ .reg .u64 t; cvta.to.shared.u64 t, %1; cvt.u32.u64 %0, t; }"
        : "=r"(a) : "l"(p));
    return a;
}
__device__ __forceinline__ void cp16(uint32_t dst, const void* src) {
    asm volatile("cp.async.cg.shared.global [%0], [%1], 16;" :: "r"(dst), "l"(src));
}
__device__ __forceinline__ void cp_commit() {
    asm volatile("cp.async.commit_group;" ::: "memory");
}
template <int N> __device__ __forceinline__ void cp_wait() {
    asm volatile("cp.async.wait_group %0;" :: "n"(N) : "memory");
}

// ============================================================
// fp32 -> fp16 conversion pass (half2 stores)
// ============================================================
__global__ void f2h_pass(const float* __restrict__ in, __half* __restrict__ out, int n2)
{
    int i = blockIdx.x * blockDim.x + threadIdx.x;
    if (i < n2) {
        float2 v = ((const float2*)in)[i];
        ((__half2*)out)[i] = __floats2half2_rn(v.x, v.y);
    }
}

// ============================================================
// fp16 wmma GEMM (round-4 config): C = A[M,768] @ W[N,768]^T (+bias)
// Tile 128x128, 8 warps (warp tile 64x32), K chunks of 64,
// cp.async double-buffered. MODE 0 also emits half Q/K (fused f2h).
// ============================================================
#define LDS_PAD 72
#define CHUNK_HALFS (128 * LDS_PAD)
#define GEMM_SMEM (4 * CHUNK_HALFS * 2)

template <int MODE>
__global__ __launch_bounds__(256) void gemm_fp16(
    const __half* __restrict__ A, const __half* __restrict__ Bw,
    const float* __restrict__ bias0, const float* __restrict__ bias1,
    float* __restrict__ outp)
{
    extern __shared__ __half hsm[];
    __half* Abuf[2] = {hsm, hsm + CHUNK_HALFS};
    __half* Bbuf[2] = {hsm + 2 * CHUNK_HALFS, hsm + 3 * CHUNK_HALFS};
    __shared__ float bias2d[16][132];
    __shared__ float stg[8][16 * 18];

    int t = threadIdx.x;
    int w = t >> 5, lid = t & 31;
    int wy = w >> 2, wx = w & 3;
    int m0 = blockIdx.y * 128, n0 = blockIdx.x * 128;

    if (t < 128) {
        int col = n0 + t;
        float bv;
        if (MODE == 0) {
            int which = col / 768, c = col - which * 768;
            bv = (which == 0) ? bias0[c] : ((which == 2) ? bias1[c] : 0.f);
        } else bv = bias0[col];
#pragma unroll
        for (int r = 0; r < 16; r++) bias2d[r][t] = bv;
    }
    __syncthreads();

    wmma::fragment<wmma::accumulator, 16, 16, 16, float> acc[4][2];
#pragma unroll
    for (int i = 0; i < 4; i++)
#pragma unroll
        for (int j = 0; j < 2; j++)
            wmma::load_matrix_sync(acc[i][j], &bias2d[0][wx * 32 + j * 16], 132,
                                   wmma::mem_row_major);

    const __half* gA = A + (size_t)m0 * 768;
    const __half* gB = Bw + (size_t)n0 * 768;
    uint32_t aS[2] = {smem_u32(Abuf[0]), smem_u32(Abuf[1])};
    uint32_t bS[2] = {smem_u32(Bbuf[0]), smem_u32(Bbuf[1])};

    auto load_chunk = [&](int kc, int p) {
#pragma unroll
        for (int j = 0; j < 4; j++) {
            int s = t + j * 256;
            int row = s >> 3, c8 = s & 7;
            cp16(aS[p] + row * (LDS_PAD * 2) + c8 * 16,
                 gA + (size_t)row * 768 + kc * 64 + c8 * 8);
            cp16(bS[p] + row * (LDS_PAD * 2) + c8 * 16,
                 gB + (size_t)row * 768 + kc * 64 + c8 * 8);
        }
        cp_commit();
    };

    load_chunk(0, 0);
    const int NCHUNK = 12;
    for (int i = 0; i < NCHUNK; i++) {
        int p = i & 1;
        if (i + 1 < NCHUNK) { load_chunk(i + 1, p ^ 1); cp_wait<1>(); }
        else cp_wait<0>();
        __syncthreads();
#pragma unroll
        for (int kk = 0; kk < 64; kk += 16) {
            wmma::fragment<wmma::matrix_a, 16, 16, 16, __half, wmma::row_major> af[4];
            wmma::fragment<wmma::matrix_b, 16, 16, 16, __half, wmma::col_major> bf[2];
#pragma unroll
            for (int q = 0; q < 4; q++)
                wmma::load_matrix_sync(af[q], &Abuf[p][(wy * 64 + q * 16) * LDS_PAD + kk],
                                       LDS_PAD);
#pragma unroll
            for (int q = 0; q < 2; q++)
                wmma::load_matrix_sync(bf[q], &Bbuf[p][(wx * 32 + q * 16) * LDS_PAD + kk],
                                       LDS_PAD);
#pragma unroll
            for (int q = 0; q < 4; q++)
#pragma unroll
                for (int r = 0; r < 2; r++)
                    wmma::mma_sync(acc[q][r], af[q], bf[r], acc[q][r]);
        }
        __syncthreads();
    }

#pragma unroll
    for (int i = 0; i < 4; i++) {
        int row0 = m0 + wy * 64 + i * 16;
#pragma unroll
        for (int j = 0; j < 2; j++) {
            int col0 = n0 + wx * 32 + j * 16;
            if (MODE == 0) {
                int b = row0 >> 10, n = row0 & 1023;
                int which = col0 / 768;
                int c = col0 - which * 768;
                int h = c >> 6, d0 = c & 63;
                size_t off = ((size_t)(b * NHEAD + h) << 16) + (n << 6) + d0;
                float* dst = (which == 0 ? g_Q : (which == 1 ? g_K : g_V)) + off;
                wmma::store_matrix_sync(dst, acc[i][j], 64, wmma::mem_row_major);
                if (which <= 1) {
                    // fused half conversion via warp-private staging
                    float* stw = &stg[w][0];
                    wmma::store_matrix_sync(stw, acc[i][j], 18, wmma::mem_row_major);
                    __syncwarp();
                    __half* dsth = (which == 0 ? g_Qh : g_Kh) + off;
                    int rr = lid >> 1, cc = (lid & 1) * 8;
                    float* sp = stw + rr * 18 + cc;
                    __half2 h0 = __floats2half2_rn(sp[0], sp[1]);
                    __half2 h1 = __floats2half2_rn(sp[2], sp[3]);
                    __half2 h2 = __floats2half2_rn(sp[4], sp[5]);
                    __half2 h3 = __floats2half2_rn(sp[6], sp[7]);
                    __half2* dp = (__half2*)(dsth + (size_t)rr * 64 + cc);
                    dp[0] = h0; dp[1] = h1; dp[2] = h2; dp[3] = h3;
                    __syncwarp();
                }
            } else {
                wmma::store_matrix_sync(outp + (size_t)row0 * 768 + col0, acc[i][j],
                                        768, wmma::mem_row_major);
            }
        }
    }
}

// ============================================================
// learned LR: eta = sigmoid(x·w_h + b_h)/64 — smem-cached weights,
// 256 blocks x 8 warps x 8 rows.
// ============================================================
__global__ __launch_bounds__(256) void lr_kernel2(
    const float* __restrict__ x, const float* __restrict__ lrw,
    const float* __restrict__ lrb)
{
    __shared__ float ws[12 * 768];
    __shared__ float lb[12];
    int t = threadIdx.x, w = t >> 5, l = t & 31;
    for (int i = t; i < 12 * 768; i += 256) ws[i] = lrw[i];
    if (t < 12) lb[t] = lrb[t];
    __syncthreads();

    int rowbase = blockIdx.x * 64 + w * 8;
    for (int rr = 0; rr < 8; rr++) {
        int row = rowbase + rr;
        const float* xr = x + (size_t)row * 768;
        float xv[24];
#pragma unroll
        for (int k = 0; k < 24; k++) xv[k] = xr[l + k * 32];
#pragma unroll
        for (int h = 0; h < 12; h++) {
            float s = 0.f;
#pragma unroll
            for (int k = 0; k < 24; k++) s = fmaf(xv[k], ws[h * 768 + l + k * 32], s);
            s = warp_sum(s);
            if (l == 0) {
                float v = 1.f / (1.f + expf(-(s + lb[h])));
                int b = row >> 10, n = row & 1023;
                g_eta[(b * NHEAD + h) * 1024 + n] = v * (1.f / 64.f);
            }
        }
    }
}

// ============================================================
// phase1 (tensor cores, 4-way split): block = (bh, part), 256 rows.
// Z1 = XK_h @ W1_h + b1 (wmma), fp32 LN-L2-bwd, g*1024 -> g_Gh (half),
// partial b1 grad sums -> g_b1part[bh][part][64].
// ============================================================
__global__ __launch_bounds__(256) void ttt_phase1_tc(
    const float* __restrict__ W1, const float* __restrict__ b1,
    const float* __restrict__ gamma, const float* __restrict__ beta)
{
    int bh = blockIdx.x >> 2, part = blockIdx.x & 3;
    int h = bh % NHEAD;
    __shared__ __half W1h[64 * 72];
    __shared__ float zs[8][16 * 68];
    __shared__ float b1s[64], gs[64], bs[64];
    __shared__ float gbacc[8 * 64];
    int t = threadIdx.x, w = t >> 5, l = t & 31;

    for (int i = t; i < 4096; i += 256) {
        int r = i >> 6, c = i & 63;
        W1h[r * 72 + c] = __float2half(W1[h * 4096 + i]);
    }
    if (t < 64) {
        b1s[t] = b1[h * 64 + t];
        gs[t]  = gamma[h * 64 + t];
        bs[t]  = beta[h * 64 + t];
    }
    __syncthreads();

    const __half* Kh = g_Kh + (size_t)bh * TOKHD;
    const float* Kp = g_K + (size_t)bh * TOKHD;
    const float* Vp = g_V + (size_t)bh * TOKHD;
    __half* Gh = g_Gh + (size_t)bh * TOKHD;
    const float* etap = g_eta + bh * 1024;

    float gb0 = 0.f, gb1 = 0.f;
    for (int s = 0; s < 2; s++) {
        int row0 = part * 256 + (s * 8 + w) * 16;
        wmma::fragment<wmma::accumulator, 16, 16, 16, float> acc[4];
#pragma unroll
        for (int n = 0; n < 4; n++) wmma::fill_fragment(acc[n], 0.f);
#pragma unroll
        for (int k = 0; k < 4; k++) {
            wmma::fragment<wmma::matrix_a, 16, 16, 16, __half, wmma::row_major> af;
            wmma::load_matrix_sync(af, Kh + (size_t)row0 * 64 + k * 16, 64);
#pragma unroll
            for (int n = 0; n < 4; n++) {
                wmma::fragment<wmma::matrix_b, 16, 16, 16, __half, wmma::row_major> bf;
                wmma::load_matrix_sync(bf, &W1h[(k * 16) * 72 + n * 16], 72);
                wmma::mma_sync(acc[n], af, bf, acc[n]);
            }
        }
#pragma unroll
        for (int n = 0; n < 4; n++)
            wmma::store_matrix_sync(&zs[w][n * 16], acc[n], 68, wmma::mem_row_major);
        __syncwarp();

#pragma unroll
        for (int r = 0; r < 16; r++) {
            int row = row0 + r;
            float z0 = zs[w][r * 68 + l] + b1s[l];
            float z1 = zs[w][r * 68 + l + 32] + b1s[l + 32];
            float mu = warp_sum(z0 + z1) * (1.f / 64.f);
            float d0 = z0 - mu, d1 = z1 - mu;
            float var = warp_sum(d0 * d0 + d1 * d1) * (1.f / 64.f);
            float rstd = rsqrtf(var + 1e-6f);
            float xh0 = d0 * rstd, xh1 = d1 * rstd;
            float xk0 = Kp[row * 64 + l], xk1 = Kp[row * 64 + l + 32];
            float xv0 = Vp[row * 64 + l], xv1 = Vp[row * 64 + l + 32];
            float go0 = gs[l] * xh0 + bs[l] - (xv0 - xk0);
            float go1 = gs[l + 32] * xh1 + bs[l + 32] - (xv1 - xk1);
            float gg0 = go0 * gs[l], gg1 = go1 * gs[l + 32];
            float sg  = warp_sum(gg0 + gg1);
            float sgx = warp_sum(gg0 * xh0 + gg1 * xh1);
            float sc  = etap[row] * rstd * (1.f / 64.f) * (1.f / 1024.f);
            float gf0 = (64.f * gg0 - sg - xh0 * sgx) * sc;
            float gf1 = (64.f * gg1 - sg - xh1 * sgx) * sc;
            Gh[row * 64 + l]      = __float2half(gf0 * 1024.f);
            Gh[row * 64 + l + 32] = __float2half(gf1 * 1024.f);
            gb0 += gf0; gb1 += gf1;
        }
    }
    gbacc[w * 64 + l] = gb0;
    gbacc[w * 64 + l + 32] = gb1;
    __syncthreads();
    if (t < 64) {
        float s = 0.f;
#pragma unroll
        for (int ww = 0; ww < 8; ww++) s += gbacc[ww * 64 + t];
        g_b1part[(bh * 4 + part) * 64 + t] = s;
    }
}

// ============================================================
// gradw (tensor cores): W1n = W1 - (XK_h^T @ g_h)/1024 (half out),
// plus final b1n reduction from the 4 partials.
// ============================================================
__global__ __launch_bounds__(256) void ttt_gradw_tc(
    const float* __restrict__ W1, const float* __restrict__ b1)
{
    int bh = blockIdx.x;
    int h = bh % NHEAD;
    __shared__ float parts[8][16 * 68];
    int t = threadIdx.x, w = t >> 5;
    int wt = w & 3, kh = w >> 2;

    const __half* Kh = g_Kh + (size_t)bh * TOKHD;
    const __half* Gh = g_Gh + (size_t)bh * TOKHD;

    wmma::fragment<wmma::accumulator, 16, 16, 16, float> acc[4];
#pragma unroll
    for (int n = 0; n < 4; n++) wmma::fill_fragment(acc[n], 0.f);

    for (int ks = 0; ks < 32; ks++) {
        int k = kh * 512 + ks * 16;
        wmma::fragment<wmma::matrix_a, 16, 16, 16, __half, wmma::col_major> af;
        wmma::load_matrix_sync(af, Kh + (size_t)k * 64 + wt * 16, 64);
#pragma unroll
        for (int n = 0; n < 4; n++) {
            wmma::fragment<wmma::matrix_b, 16, 16, 16, __half, wmma::row_major> bf;
            wmma::load_matrix_sync(bf, Gh + (size_t)k * 64 + n * 16, 64);
            wmma::mma_sync(acc[n], af, bf, acc[n]);
        }
    }
#pragma unroll
    for (int n = 0; n < 4; n++)
        wmma::store_matrix_sync(&parts[w][n * 16], acc[n], 68, wmma::mem_row_major);
    __syncthreads();

    if (t < 64) {
        float s = g_b1part[(bh * 4 + 0) * 64 + t] + g_b1part[(bh * 4 + 1) * 64 + t]
                + g_b1part[(bh * 4 + 2) * 64 + t] + g_b1part[(bh * 4 + 3) * 64 + t];
        g_b1n[bh * 64 + t] = b1[h * 64 + t] - s;
    }

    for (int i = t; i < 4096; i += 256) {
        int d = i >> 6, e = i & 63;
        int wt2 = d >> 4, r = d & 15;
        float gsum = parts[wt2][r * 68 + e] + parts[wt2 + 4][r * 68 + e];
        g_W1nh[(size_t)bh * 4096 + i] =
            __float2half(W1[h * 4096 + i] - gsum * (1.f / 1024.f));
    }
}

// ============================================================
// phase3 (tensor cores, 4-way split): block = (bh, part), 256 rows.
// Z = XQ_h @ W1n_h + b1n, fp32 LN fwd, out = XQ + y -> g_XQWh.
// ============================================================
__global__ __launch_bounds__(256) void ttt_phase3_tc(
    const float* __restrict__ gamma, const float* __restrict__ beta)
{
    int bh = blockIdx.x >> 2, part = blockIdx.x & 3;
    int h = bh % NHEAD, b = bh / NHEAD;
    __shared__ __half W1h[64 * 72];
    __shared__ float zs[8][16 * 68];
    __shared__ float b1s[64], gs[64], bs[64];
    int t = threadIdx.x, w = t >> 5, l = t & 31;

    for (int i = t; i < 4096; i += 256) {
        int r = i >> 6, c = i & 63;
        W1h[r * 72 + c] = g_W1nh[(size_t)bh * 4096 + i];
    }
    if (t < 64) {
        b1s[t] = g_b1n[bh * 64 + t];
        gs[t]  = gamma[h * 64 + t];
        bs[t]  = beta[h * 64 + t];
    }
    __syncthreads();

    const __half* Qh = g_Qh + (size_t)bh * TOKHD;
    const float* Qp = g_Q + (size_t)bh * TOKHD;
    __half* Op = g_XQWh + (size_t)b * 1024 * CDIM;

    for (int s = 0; s < 2; s++) {
        int row0 = part * 256 + (s * 8 + w) * 16;
        wmma::fragment<wmma::accumulator, 16, 16, 16, float> acc[4];
#pragma unroll
        for (int n = 0; n < 4; n++) wmma::fill_fragment(acc[n], 0.f);
#pragma unroll
        for (int k = 0; k < 4; k++) {
            wmma::fragment<wmma::matrix_a, 16, 16, 16, __half, wmma::row_major> af;
            wmma::load_matrix_sync(af, Qh + (size_t)row0 * 64 + k * 16, 64);
#pragma unroll
            for (int n = 0; n < 4; n++) {
                wmma::fragment<wmma::matrix_b, 16, 16, 16, __half, wmma::row_major> bf;
                wmma::load_matrix_sync(bf, &W1h[(k * 16) * 72 + n * 16], 72);
                wmma::mma_sync(acc[n], af, bf, acc[n]);
            }
        }
#pragma unroll
        for (int n = 0; n < 4; n++)
            wmma::store_matrix_sync(&zs[w][n * 16], acc[n], 68, wmma::mem_row_major);
        __syncwarp();

#pragma unroll
        for (int r = 0; r < 16; r++) {
            int row = row0 + r;
            float z0 = zs[w][r * 68 + l] + b1s[l];
            float z1 = zs[w][r * 68 + l + 32] + b1s[l + 32];
            float mu = warp_sum(z0 + z1) * (1.f / 64.f);
            float d0 = z0 - mu, d1 = z1 - mu;
            float var = warp_sum(d0 * d0 + d1 * d1) * (1.f / 64.f);
            float rstd = rsqrtf(var + 1e-6f);
            float y0 = gs[l] * (d0 * rstd) + bs[l];
            float y1 = gs[l + 32] * (d1 * rstd) + bs[l + 32];
            float xq0 = Qp[row * 64 + l], xq1 = Qp[row * 64 + l + 32];
            Op[row * CDIM + h * 64 + l]      = __float2half(xq0 + y0);
            Op[row * CDIM + h * 64 + l + 32] = __float2half(xq1 + y1);
        }
    }
}

// ============================================================
extern "C" void kernel_launch(void* const* d_in, const int* in_sizes, int n_in,
                              void* d_out, int out_size)
{
    (void)in_sizes; (void)n_in; (void)out_size;
    const float* x     = (const float*)d_in[0];
    const float* qkvw  = (const float*)d_in[1];
    const float* qb    = (const float*)d_in[2];
    const float* vb    = (const float*)d_in[3];
    const float* pw    = (const float*)d_in[4];
    const float* pb    = (const float*)d_in[5];
    const float* lrw   = (const float*)d_in[6];
    const float* lrb   = (const float*)d_in[7];
    const float* gamma = (const float*)d_in[8];
    const float* beta  = (const float*)d_in[9];
    const float* W1    = (const float*)d_in[10];
    const float* b1    = (const float*)d_in[11];
    float* out = (float*)d_out;

    cudaFuncSetAttribute(gemm_fp16<0>, cudaFuncAttributeMaxDynamicSharedMemorySize, GEMM_SMEM);
    cudaFuncSetAttribute(gemm_fp16<1>, cudaFuncAttributeMaxDynamicSharedMemorySize, GEMM_SMEM);

    __half *Xh, *Wqh, *Wph, *XQWh;
    cudaGetSymbolAddress((void**)&Xh, g_Xh);
    cudaGetSymbolAddress((void**)&Wqh, g_Wqh);
    cudaGetSymbolAddress((void**)&Wph, g_Wph);
    cudaGetSymbolAddress((void**)&XQWh, g_XQWh);

    f2h_pass<<<(6291456 + 255) / 256, 256>>>(x, Xh, 6291456);
    f2h_pass<<<(884736 + 255) / 256, 256>>>(qkvw, Wqh, 884736);
    f2h_pass<<<(294912 + 255) / 256, 256>>>(pw, Wph, 294912);

    gemm_fp16<0><<<dim3(18, 128), 256, GEMM_SMEM>>>(Xh, Wqh, qb, vb, nullptr);

    lr_kernel2<<<256, 256>>>(x, lrw, lrb);
    ttt_phase1_tc<<<768, 256>>>(W1, b1, gamma, beta);
    ttt_gradw_tc<<<192, 256>>>(W1, b1);
    ttt_phase3_tc<<<768, 256>>>(gamma, beta);

    gemm_fp16<1><<<dim3(6, 128), 256, GEMM_SMEM>>>(XQWh, Wph, pb, nullptr, out);
}

// round 8
// speedup vs baseline: 4.2148x; 1.0385x over previous
#include <cuda_runtime.h>
#include <cuda_fp16.h>
#include <mma.h>
#include <math.h>
#include <stdint.h>

using namespace nvcuda;

// Problem constants: B=16, N=1024, C=768, H=12, HD=64, one mini-batch (m=1024)
#define NTOK   16384
#define CDIM   768
#define NHEAD  12
#define HD     64
#define BH     192
#define TOKHD  65536          // 1024*64 per (b,h)

// ---- scratch (static device globals; no allocations anywhere) ----
__device__ float  g_eta[196608];     // [B,H,N]
__device__ float  g_b1n[12288];      // [BH,64]
__device__ float  g_b1part[49152];   // [BH,4,64] partial b1 grad sums
__device__ float  g_W1part[3145728]; // [BH,4,64,64] partial W1 grads
__device__ __half g_Xh[12582912];    // half(x) [16384,768]
__device__ __half g_Wqh[1769472];    // half(qkv_weight) [2304,768]
__device__ __half g_Wph[589824];     // half(proj_weight) [768,768]
__device__ __half g_XQWh[12582912];  // half pre-projection [B,N,C]
__device__ __half g_Qh[12582912];    // half Q [B,H,N,64]
__device__ __half g_Kh[12582912];    // half K
__device__ __half g_Vh[12582912];    // half V
__device__ __half g_Gh[12582912];    // half g scaled by 1024
__device__ __half g_W1nh[786432];    // half W1n [BH,64,64]

__device__ __forceinline__ float warp_sum(float v) {
#pragma unroll
    for (int o = 16; o > 0; o >>= 1) v += __shfl_xor_sync(0xffffffffu, v, o);
    return v;
}
__device__ __forceinline__ uint32_t smem_u32(const void* p) {
    uint32_t a;
    asm("{ .reg .u64 t; cvta.to.shared.u64 t, %1; cvt.u32.u64 %0, t; }"
        : "=r"(a) : "l"(p));
    return a;
}
__device__ __forceinline__ void cp16(uint32_t dst, const void* src) {
    asm volatile("cp.async.cg.shared.global [%0], [%1], 16;" :: "r"(dst), "l"(src));
}
__device__ __forceinline__ void cp_commit() {
    asm volatile("cp.async.commit_group;" ::: "memory");
}
template <int N> __device__ __forceinline__ void cp_wait() {
    asm volatile("cp.async.wait_group %0;" :: "n"(N) : "memory");
}

// ============================================================
// fp32 -> fp16 conversion pass (half2 stores)
// ============================================================
__global__ void f2h_pass(const float* __restrict__ in, __half* __restrict__ out, int n2)
{
    int i = blockIdx.x * blockDim.x + threadIdx.x;
    if (i < n2) {
        float2 v = ((const float2*)in)[i];
        ((__half2*)out)[i] = __floats2half2_rn(v.x, v.y);
    }
}

// ============================================================
// fp16 wmma GEMM: C = A[M,768] @ W[N,768]^T (+bias)
// Tile 128x128, 8 warps (warp tile 64x32), K chunks of 64,
// cp.async double-buffered.
// MODE 0: write HALF-ONLY Q/K/V into g_Qh/g_Kh/g_Vh [B,H,N,64] (+bias).
// MODE 1: direct fp32 store to outp [M,768] (+bias).
// ============================================================
#define LDS_PAD 72
#define CHUNK_HALFS (128 * LDS_PAD)
#define GEMM_SMEM (4 * CHUNK_HALFS * 2)

template <int MODE>
__global__ __launch_bounds__(256) void gemm_fp16(
    const __half* __restrict__ A, const __half* __restrict__ Bw,
    const float* __restrict__ bias0, const float* __restrict__ bias1,
    float* __restrict__ outp)
{
    extern __shared__ __half hsm[];
    __half* Abuf[2] = {hsm, hsm + CHUNK_HALFS};
    __half* Bbuf[2] = {hsm + 2 * CHUNK_HALFS, hsm + 3 * CHUNK_HALFS};
    __shared__ float bias2d[16][132];
    __shared__ float stg[8][16 * 18];

    int t = threadIdx.x;
    int w = t >> 5, lid = t & 31;
    int wy = w >> 2, wx = w & 3;
    int m0 = blockIdx.y * 128, n0 = blockIdx.x * 128;

    if (t < 128) {
        int col = n0 + t;
        float bv;
        if (MODE == 0) {
            int which = col / 768, c = col - which * 768;
            bv = (which == 0) ? bias0[c] : ((which == 2) ? bias1[c] : 0.f);
        } else bv = bias0[col];
#pragma unroll
        for (int r = 0; r < 16; r++) bias2d[r][t] = bv;
    }
    __syncthreads();

    wmma::fragment<wmma::accumulator, 16, 16, 16, float> acc[4][2];
#pragma unroll
    for (int i = 0; i < 4; i++)
#pragma unroll
        for (int j = 0; j < 2; j++)
            wmma::load_matrix_sync(acc[i][j], &bias2d[0][wx * 32 + j * 16], 132,
                                   wmma::mem_row_major);

    const __half* gA = A + (size_t)m0 * 768;
    const __half* gB = Bw + (size_t)n0 * 768;
    uint32_t aS[2] = {smem_u32(Abuf[0]), smem_u32(Abuf[1])};
    uint32_t bS[2] = {smem_u32(Bbuf[0]), smem_u32(Bbuf[1])};

    auto load_chunk = [&](int kc, int p) {
#pragma unroll
        for (int j = 0; j < 4; j++) {
            int s = t + j * 256;
            int row = s >> 3, c8 = s & 7;
            cp16(aS[p] + row * (LDS_PAD * 2) + c8 * 16,
                 gA + (size_t)row * 768 + kc * 64 + c8 * 8);
            cp16(bS[p] + row * (LDS_PAD * 2) + c8 * 16,
                 gB + (size_t)row * 768 + kc * 64 + c8 * 8);
        }
        cp_commit();
    };

    load_chunk(0, 0);
    const int NCHUNK = 12;
    for (int i = 0; i < NCHUNK; i++) {
        int p = i & 1;
        if (i + 1 < NCHUNK) { load_chunk(i + 1, p ^ 1); cp_wait<1>(); }
        else cp_wait<0>();
        __syncthreads();
#pragma unroll
        for (int kk = 0; kk < 64; kk += 16) {
            wmma::fragment<wmma::matrix_a, 16, 16, 16, __half, wmma::row_major> af[4];
            wmma::fragment<wmma::matrix_b, 16, 16, 16, __half, wmma::col_major> bf[2];
#pragma unroll
            for (int q = 0; q < 4; q++)
                wmma::load_matrix_sync(af[q], &Abuf[p][(wy * 64 + q * 16) * LDS_PAD + kk],
                                       LDS_PAD);
#pragma unroll
            for (int q = 0; q < 2; q++)
                wmma::load_matrix_sync(bf[q], &Bbuf[p][(wx * 32 + q * 16) * LDS_PAD + kk],
                                       LDS_PAD);
#pragma unroll
            for (int q = 0; q < 4; q++)
#pragma unroll
                for (int r = 0; r < 2; r++)
                    wmma::mma_sync(acc[q][r], af[q], bf[r], acc[q][r]);
        }
        __syncthreads();
    }

#pragma unroll
    for (int i = 0; i < 4; i++) {
        int row0 = m0 + wy * 64 + i * 16;
#pragma unroll
        for (int j = 0; j < 2; j++) {
            int col0 = n0 + wx * 32 + j * 16;
            if (MODE == 0) {
                int b = row0 >> 10, n = row0 & 1023;
                int which = col0 / 768;
                int c = col0 - which * 768;
                int h = c >> 6, d0 = c & 63;
                size_t off = ((size_t)(b * NHEAD + h) << 16) + (n << 6) + d0;
                __half* dsth = (which == 0 ? g_Qh : (which == 1 ? g_Kh : g_Vh)) + off;
                float* stw = &stg[w][0];
                wmma::store_matrix_sync(stw, acc[i][j], 18, wmma::mem_row_major);
                __syncwarp();
                int rr = lid >> 1, cc = (lid & 1) * 8;
                float* sp = stw + rr * 18 + cc;
                __half2 h0 = __floats2half2_rn(sp[0], sp[1]);
                __half2 h1 = __floats2half2_rn(sp[2], sp[3]);
                __half2 h2 = __floats2half2_rn(sp[4], sp[5]);
                __half2 h3 = __floats2half2_rn(sp[6], sp[7]);
                __half2* dp = (__half2*)(dsth + (size_t)rr * 64 + cc);
                dp[0] = h0; dp[1] = h1; dp[2] = h2; dp[3] = h3;
                __syncwarp();
            } else {
                wmma::store_matrix_sync(outp + (size_t)row0 * 768 + col0, acc[i][j],
                                        768, wmma::mem_row_major);
            }
        }
    }
}

// ============================================================
// learned LR: eta = sigmoid(x·w_h + b_h)/64 — smem-cached weights
// ============================================================
__global__ __launch_bounds__(256) void lr_kernel2(
    const float* __restrict__ x, const float* __restrict__ lrw,
    const float* __restrict__ lrb)
{
    __shared__ float ws[12 * 768];
    __shared__ float lb[12];
    int t = threadIdx.x, w = t >> 5, l = t & 31;
    for (int i = t; i < 12 * 768; i += 256) ws[i] = lrw[i];
    if (t < 12) lb[t] = lrb[t];
    __syncthreads();

    int rowbase = blockIdx.x * 64 + w * 8;
    for (int rr = 0; rr < 8; rr++) {
        int row = rowbase + rr;
        const float* xr = x + (size_t)row * 768;
        float xv[24];
#pragma unroll
        for (int k = 0; k < 24; k++) xv[k] = xr[l + k * 32];
#pragma unroll
        for (int h = 0; h < 12; h++) {
            float s = 0.f;
#pragma unroll
            for (int k = 0; k < 24; k++) s = fmaf(xv[k], ws[h * 768 + l + k * 32], s);
            s = warp_sum(s);
            if (l == 0) {
                float v = 1.f / (1.f + expf(-(s + lb[h])));
                int b = row >> 10, n = row & 1023;
                g_eta[(b * NHEAD + h) * 1024 + n] = v * (1.f / 64.f);
            }
        }
    }
}

// ============================================================
// phase1 (tensor cores, 4-way split): block = (bh, part), 256 rows.
// Z1 = XK_h @ W1_h + b1 (wmma), fp32 LN-L2-bwd, g*1024 -> g_Gh (half),
// partial b1 grad sums -> g_b1part[bh][part][64].
// K/V read from half arrays.
// ============================================================
__global__ __launch_bounds__(256) void ttt_phase1_tc(
    const float* __restrict__ W1, const float* __restrict__ b1,
    const float* __restrict__ gamma, const float* __restrict__ beta)
{
    int bh = blockIdx.x >> 2, part = blockIdx.x & 3;
    int h = bh % NHEAD;
    __shared__ __half W1h[64 * 72];
    __shared__ float zs[8][16 * 68];
    __shared__ float b1s[64], gs[64], bs[64];
    __shared__ float gbacc[8 * 64];
    int t = threadIdx.x, w = t >> 5, l = t & 31;

    for (int i = t; i < 4096; i += 256) {
        int r = i >> 6, c = i & 63;
        W1h[r * 72 + c] = __float2half(W1[h * 4096 + i]);
    }
    if (t < 64) {
        b1s[t] = b1[h * 64 + t];
        gs[t]  = gamma[h * 64 + t];
        bs[t]  = beta[h * 64 + t];
    }
    __syncthreads();

    const __half* Kh = g_Kh + (size_t)bh * TOKHD;
    const __half* Vh = g_Vh + (size_t)bh * TOKHD;
    __half* Gh = g_Gh + (size_t)bh * TOKHD;
    const float* etap = g_eta + bh * 1024;

    float gb0 = 0.f, gb1 = 0.f;
    for (int s = 0; s < 2; s++) {
        int row0 = part * 256 + (s * 8 + w) * 16;
        wmma::fragment<wmma::accumulator, 16, 16, 16, float> acc[4];
#pragma unroll
        for (int n = 0; n < 4; n++) wmma::fill_fragment(acc[n], 0.f);
#pragma unroll
        for (int k = 0; k < 4; k++) {
            wmma::fragment<wmma::matrix_a, 16, 16, 16, __half, wmma::row_major> af;
            wmma::load_matrix_sync(af, Kh + (size_t)row0 * 64 + k * 16, 64);
#pragma unroll
            for (int n = 0; n < 4; n++) {
                wmma::fragment<wmma::matrix_b, 16, 16, 16, __half, wmma::row_major> bf;
                wmma::load_matrix_sync(bf, &W1h[(k * 16) * 72 + n * 16], 72);
                wmma::mma_sync(acc[n], af, bf, acc[n]);
            }
        }
#pragma unroll
        for (int n = 0; n < 4; n++)
            wmma::store_matrix_sync(&zs[w][n * 16], acc[n], 68, wmma::mem_row_major);
        __syncwarp();

#pragma unroll
        for (int r = 0; r < 16; r++) {
            int row = row0 + r;
            float z0 = zs[w][r * 68 + l] + b1s[l];
            float z1 = zs[w][r * 68 + l + 32] + b1s[l + 32];
            float mu = warp_sum(z0 + z1) * (1.f / 64.f);
            float d0 = z0 - mu, d1 = z1 - mu;
            float var = warp_sum(d0 * d0 + d1 * d1) * (1.f / 64.f);
            float rstd = rsqrtf(var + 1e-6f);
            float xh0 = d0 * rstd, xh1 = d1 * rstd;
            float xk0 = __half2float(Kh[row * 64 + l]);
            float xk1 = __half2float(Kh[row * 64 + l + 32]);
            float xv0 = __half2float(Vh[row * 64 + l]);
            float xv1 = __half2float(Vh[row * 64 + l + 32]);
            float go0 = gs[l] * xh0 + bs[l] - (xv0 - xk0);
            float go1 = gs[l + 32] * xh1 + bs[l + 32] - (xv1 - xk1);
            float gg0 = go0 * gs[l], gg1 = go1 * gs[l + 32];
            float sg  = warp_sum(gg0 + gg1);
            float sgx = warp_sum(gg0 * xh0 + gg1 * xh1);
            float sc  = etap[row] * rstd * (1.f / 64.f) * (1.f / 1024.f);
            float gf0 = (64.f * gg0 - sg - xh0 * sgx) * sc;
            float gf1 = (64.f * gg1 - sg - xh1 * sgx) * sc;
            Gh[row * 64 + l]      = __float2half(gf0 * 1024.f);
            Gh[row * 64 + l + 32] = __float2half(gf1 * 1024.f);
            gb0 += gf0; gb1 += gf1;
        }
    }
    gbacc[w * 64 + l] = gb0;
    gbacc[w * 64 + l + 32] = gb1;
    __syncthreads();
    if (t < 64) {
        float s = 0.f;
#pragma unroll
        for (int ww = 0; ww < 8; ww++) s += gbacc[ww * 64 + t];
        g_b1part[(bh * 4 + part) * 64 + t] = s;
    }
}

// ============================================================
// gradw part (4-way K split): partial XK^T @ g over rows
// [kp*256,(kp+1)*256) -> g_W1part[bh][kp][4096] (fp32).
// ============================================================
__global__ __launch_bounds__(256) void ttt_gradw_part()
{
    int bh = blockIdx.x >> 2, kp = blockIdx.x & 3;
    __shared__ float parts[8][16 * 68];
    int t = threadIdx.x, w = t >> 5;
    int wt = w & 3, kh = w >> 2;

    const __half* Kh = g_Kh + (size_t)bh * TOKHD + kp * 256 * 64;
    const __half* Gh = g_Gh + (size_t)bh * TOKHD + kp * 256 * 64;

    wmma::fragment<wmma::accumulator, 16, 16, 16, float> acc[4];
#pragma unroll
    for (int n = 0; n < 4; n++) wmma::fill_fragment(acc[n], 0.f);

#pragma unroll
    for (int ks = 0; ks < 8; ks++) {
        int k = kh * 128 + ks * 16;
        wmma::fragment<wmma::matrix_a, 16, 16, 16, __half, wmma::col_major> af;
        wmma::load_matrix_sync(af, Kh + (size_t)k * 64 + wt * 16, 64);
#pragma unroll
        for (int n = 0; n < 4; n++) {
            wmma::fragment<wmma::matrix_b, 16, 16, 16, __half, wmma::row_major> bf;
            wmma::load_matrix_sync(bf, Gh + (size_t)k * 64 + n * 16, 64);
            wmma::mma_sync(acc[n], af, bf, acc[n]);
        }
    }
#pragma unroll
    for (int n = 0; n < 4; n++)
        wmma::store_matrix_sync(&parts[w][n * 16], acc[n], 68, wmma::mem_row_major);
    __syncthreads();

    float* dst = g_W1part + (size_t)(bh * 4 + kp) * 4096;
    for (int i = t; i < 4096; i += 256) {
        int d = i >> 6, e = i & 63;
        int wt2 = d >> 4, r = d & 15;
        dst[i] = parts[wt2][r * 68 + e] + parts[wt2 + 4][r * 68 + e];
    }
}

// ============================================================
// combine: W1nh = half(W1 - sum_kp(W1part)/1024); b1n = b1 - sum(b1part)
// ============================================================
__global__ __launch_bounds__(256) void ttt_combine(
    const float* __restrict__ W1, const float* __restrict__ b1)
{
    int bh = blockIdx.x;
    int h = bh % NHEAD;
    int t = threadIdx.x;
    if (t < 64) {
        float s = g_b1part[(bh * 4 + 0) * 64 + t] + g_b1part[(bh * 4 + 1) * 64 + t]
                + g_b1part[(bh * 4 + 2) * 64 + t] + g_b1part[(bh * 4 + 3) * 64 + t];
        g_b1n[bh * 64 + t] = b1[h * 64 + t] - s;
    }
    const float* p0 = g_W1part + (size_t)(bh * 4 + 0) * 4096;
    const float* p1 = g_W1part + (size_t)(bh * 4 + 1) * 4096;
    const float* p2 = g_W1part + (size_t)(bh * 4 + 2) * 4096;
    const float* p3 = g_W1part + (size_t)(bh * 4 + 3) * 4096;
    for (int i = t; i < 4096; i += 256) {
        float s = p0[i] + p1[i] + p2[i] + p3[i];
        g_W1nh[(size_t)bh * 4096 + i] =
            __float2half(W1[h * 4096 + i] - s * (1.f / 1024.f));
    }
}

// ============================================================
// phase3 (tensor cores, 4-way split): Z = XQ_h @ W1n_h + b1n,
// fp32 LN fwd, out = XQ_h + y -> g_XQWh (half, [B,N,C]).
// ============================================================
__global__ __launch_bounds__(256) void ttt_phase3_tc(
    const float* __restrict__ gamma, const float* __restrict__ beta)
{
    int bh = blockIdx.x >> 2, part = blockIdx.x & 3;
    int h = bh % NHEAD, b = bh / NHEAD;
    __shared__ __half W1h[64 * 72];
    __shared__ float zs[8][16 * 68];
    __shared__ float b1s[64], gs[64], bs[64];
    int t = threadIdx.x, w = t >> 5, l = t & 31;

    for (int i = t; i < 4096; i += 256) {
        int r = i >> 6, c = i & 63;
        W1h[r * 72 + c] = g_W1nh[(size_t)bh * 4096 + i];
    }
    if (t < 64) {
        b1s[t] = g_b1n[bh * 64 + t];
        gs[t]  = gamma[h * 64 + t];
        bs[t]  = beta[h * 64 + t];
    }
    __syncthreads();

    const __half* Qh = g_Qh + (size_t)bh * TOKHD;
    __half* Op = g_XQWh + (size_t)b * 1024 * CDIM;

    for (int s = 0; s < 2; s++) {
        int row0 = part * 256 + (s * 8 + w) * 16;
        wmma::fragment<wmma::accumulator, 16, 16, 16, float> acc[4];
#pragma unroll
        for (int n = 0; n < 4; n++) wmma::fill_fragment(acc[n], 0.f);
#pragma unroll
        for (int k = 0; k < 4; k++) {
            wmma::fragment<wmma::matrix_a, 16, 16, 16, __half, wmma::row_major> af;
            wmma::load_matrix_sync(af, Qh + (size_t)row0 * 64 + k * 16, 64);
#pragma unroll
            for (int n = 0; n < 4; n++) {
                wmma::fragment<wmma::matrix_b, 16, 16, 16, __half, wmma::row_major> bf;
                wmma::load_matrix_sync(bf, &W1h[(k * 16) * 72 + n * 16], 72);
                wmma::mma_sync(acc[n], af, bf, acc[n]);
            }
        }
#pragma unroll
        for (int n = 0; n < 4; n++)
            wmma::store_matrix_sync(&zs[w][n * 16], acc[n], 68, wmma::mem_row_major);
        __syncwarp();

#pragma unroll
        for (int r = 0; r < 16; r++) {
            int row = row0 + r;
            float z0 = zs[w][r * 68 + l] + b1s[l];
            float z1 = zs[w][r * 68 + l + 32] + b1s[l + 32];
            float mu = warp_sum(z0 + z1) * (1.f / 64.f);
            float d0 = z0 - mu, d1 = z1 - mu;
            float var = warp_sum(d0 * d0 + d1 * d1) * (1.f / 64.f);
            float rstd = rsqrtf(var + 1e-6f);
            float y0 = gs[l] * (d0 * rstd) + bs[l];
            float y1 = gs[l + 32] * (d1 * rstd) + bs[l + 32];
            float xq0 = __half2float(Qh[row * 64 + l]);
            float xq1 = __half2float(Qh[row * 64 + l + 32]);
            Op[row * CDIM + h * 64 + l]      = __float2half(xq0 + y0);
            Op[row * CDIM + h * 64 + l + 32] = __float2half(xq1 + y1);
        }
    }
}

// ============================================================
extern "C" void kernel_launch(void* const* d_in, const int* in_sizes, int n_in,
                              void* d_out, int out_size)
{
    (void)in_sizes; (void)n_in; (void)out_size;
    const float* x     = (const float*)d_in[0];
    const float* qkvw  = (const float*)d_in[1];
    const float* qb    = (const float*)d_in[2];
    const float* vb    = (const float*)d_in[3];
    const float* pw    = (const float*)d_in[4];
    const float* pb    = (const float*)d_in[5];
    const float* lrw   = (const float*)d_in[6];
    const float* lrb   = (const float*)d_in[7];
    const float* gamma = (const float*)d_in[8];
    const float* beta  = (const float*)d_in[9];
    const float* W1    = (const float*)d_in[10];
    const float* b1    = (const float*)d_in[11];
    float* out = (float*)d_out;

    cudaFuncSetAttribute(gemm_fp16<0>, cudaFuncAttributeMaxDynamicSharedMemorySize, GEMM_SMEM);
    cudaFuncSetAttribute(gemm_fp16<1>, cudaFuncAttributeMaxDynamicSharedMemorySize, GEMM_SMEM);

    __half *Xh, *Wqh, *Wph, *XQWh;
    cudaGetSymbolAddress((void**)&Xh, g_Xh);
    cudaGetSymbolAddress((void**)&Wqh, g_Wqh);
    cudaGetSymbolAddress((void**)&Wph, g_Wph);
    cudaGetSymbolAddress((void**)&XQWh, g_XQWh);

    f2h_pass<<<(6291456 + 255) / 256, 256>>>(x, Xh, 6291456);
    f2h_pass<<<(884736 + 255) / 256, 256>>>(qkvw, Wqh, 884736);
    f2h_pass<<<(294912 + 255) / 256, 256>>>(pw, Wph, 294912);

    gemm_fp16<0><<<dim3(18, 128), 256, GEMM_SMEM>>>(Xh, Wqh, qb, vb, nullptr);

    lr_kernel2<<<256, 256>>>(x, lrw, lrb);
    ttt_phase1_tc<<<768, 256>>>(W1, b1, gamma, beta);
    ttt_gradw_part<<<768, 256>>>();
    ttt_combine<<<192, 256>>>(W1, b1);
    ttt_phase3_tc<<<768, 256>>>(gamma, beta);

    gemm_fp16<1><<<dim3(6, 128), 256, GEMM_SMEM>>>(XQWh, Wph, pb, nullptr, out);
}

// round 9
// speedup vs baseline: 4.4852x; 1.0642x over previous
#include <cuda_runtime.h>
#include <cuda_fp16.h>
#include <mma.h>
#include <math.h>
#include <stdint.h>

using namespace nvcuda;

// Problem constants: B=16, N=1024, C=768, H=12, HD=64, one mini-batch (m=1024)
#define NTOK   16384
#define CDIM   768
#define NHEAD  12
#define HD     64
#define BH     192
#define TOKHD  65536          // 1024*64 per (b,h)

// ---- scratch (static device globals; no allocations anywhere) ----
__device__ float  g_eta[196608];     // [B,H,N]
__device__ float  g_b1n[12288];      // [BH,64]
__device__ float  g_b1part[49152];   // [BH,4,64] partial b1 grad sums
__device__ float  g_W1part[3145728]; // [BH,4,64,64] partial W1 grads
__device__ __half g_Xh[12582912];    // half(x) [16384,768]
__device__ __half g_Wqh[1769472];    // half(qkv_weight) [2304,768]
__device__ __half g_Wph[589824];     // half(proj_weight) [768,768]
__device__ __half g_XQWh[12582912];  // half pre-projection [B,N,C]
__device__ __half g_Qh[12582912];    // half Q [B,H,N,64]
__device__ __half g_Kh[12582912];    // half K
__device__ __half g_Vh[12582912];    // half V
__device__ __half g_Gh[12582912];    // half g scaled by 1024
__device__ __half g_W1nh[786432];    // half W1n [BH,64,64]

__device__ __forceinline__ float warp_sum(float v) {
#pragma unroll
    for (int o = 16; o > 0; o >>= 1) v += __shfl_xor_sync(0xffffffffu, v, o);
    return v;
}
__device__ __forceinline__ uint32_t smem_u32(const void* p) {
    uint32_t a;
    asm("{ .reg .u64 t; cvta.to.shared.u64 t, %1; cvt.u32.u64 %0, t; }"
        : "=r"(a) : "l"(p));
    return a;
}
__device__ __forceinline__ void cp16(uint32_t dst, const void* src) {
    asm volatile("cp.async.cg.shared.global [%0], [%1], 16;" :: "r"(dst), "l"(src));
}
__device__ __forceinline__ void cp_commit() {
    asm volatile("cp.async.commit_group;" ::: "memory");
}
template <int N> __device__ __forceinline__ void cp_wait() {
    asm volatile("cp.async.wait_group %0;" :: "n"(N) : "memory");
}

// ============================================================
// fp32 -> fp16 conversion pass (half2 stores)
// ============================================================
__global__ void f2h_pass(const float* __restrict__ in, __half* __restrict__ out, int n2)
{
    int i = blockIdx.x * blockDim.x + threadIdx.x;
    if (i < n2) {
        float2 v = ((const float2*)in)[i];
        ((__half2*)out)[i] = __floats2half2_rn(v.x, v.y);
    }
}

// ============================================================
// fp16 wmma GEMM: C = A[M,768] @ W[N,768]^T (+bias)
// Tile 128x128, 8 warps (warp tile 64x32).
// K chunks of 32 halfs, 3-stage cp.async pipeline => ~60KB dynamic smem,
// union'ed bias/staging => 2 CTAs per SM (16 warps) for latency hiding.
// MODE 0: write HALF-ONLY Q/K/V into g_Qh/g_Kh/g_Vh [B,H,N,64] (+bias).
// MODE 1: direct fp32 store to outp [M,768] (+bias).
// ============================================================
#define KCH 32
#define KPAD 40                        // halfs per row (64B data + 16B pad)
#define BUF_HALFS (128 * KPAD)         // 5120 halfs per matrix per stage
#define NSTAGE 3
#define GEMM_SMEM (NSTAGE * 2 * BUF_HALFS * 2)   // 61440 bytes

template <int MODE>
__global__ __launch_bounds__(256, 2) void gemm_fp16(
    const __half* __restrict__ A, const __half* __restrict__ Bw,
    const float* __restrict__ bias0, const float* __restrict__ bias1,
    float* __restrict__ outp)
{
    extern __shared__ __half hsm[];
    __shared__ union {
        float bias2d[16][132];
        float stg[8][16 * 18];
    } u;

    int t = threadIdx.x;
    int w = t >> 5, lid = t & 31;
    int wy = w >> 2, wx = w & 3;          // warp tile 64(m) x 32(n)
    int m0 = blockIdx.y * 128, n0 = blockIdx.x * 128;

    if (t < 128) {
        int col = n0 + t;
        float bv;
        if (MODE == 0) {
            int which = col / 768, c = col - which * 768;
            bv = (which == 0) ? bias0[c] : ((which == 2) ? bias1[c] : 0.f);
        } else bv = bias0[col];
#pragma unroll
        for (int r = 0; r < 16; r++) u.bias2d[r][t] = bv;
    }
    __syncthreads();

    wmma::fragment<wmma::accumulator, 16, 16, 16, float> acc[4][2];
#pragma unroll
    for (int i = 0; i < 4; i++)
#pragma unroll
        for (int j = 0; j < 2; j++)
            wmma::load_matrix_sync(acc[i][j], &u.bias2d[0][wx * 32 + j * 16], 132,
                                   wmma::mem_row_major);
    __syncthreads();   // done with bias buffer before staging reuse

    const __half* gA = A + (size_t)m0 * 768;
    const __half* gB = Bw + (size_t)n0 * 768;

    auto stA = [&](int s) -> __half* { return hsm + s * 2 * BUF_HALFS; };
    auto stB = [&](int s) -> __half* { return hsm + s * 2 * BUF_HALFS + BUF_HALFS; };

    auto load_chunk = [&](int kc, int s) {
        uint32_t aS = smem_u32(stA(s));
        uint32_t bS = smem_u32(stB(s));
#pragma unroll
        for (int j = 0; j < 2; j++) {
            int idx = t + j * 256;              // 0..511
            int row = idx >> 2, c4 = idx & 3;   // 4 x 16B per 64B row
            cp16(aS + row * (KPAD * 2) + c4 * 16,
                 gA + (size_t)row * 768 + kc * KCH + c4 * 8);
            cp16(bS + row * (KPAD * 2) + c4 * 16,
                 gB + (size_t)row * 768 + kc * KCH + c4 * 8);
        }
        cp_commit();
    };

    const int NCHUNK = 24;                      // 768/32
    load_chunk(0, 0);
    load_chunk(1, 1);
    for (int i = 0; i < NCHUNK; i++) {
        int s = i % NSTAGE;
        if (i + 2 < NCHUNK) { load_chunk(i + 2, (i + 2) % NSTAGE); cp_wait<2>(); }
        else if (i + 1 < NCHUNK) cp_wait<1>();
        else cp_wait<0>();
        __syncthreads();

        __half* As = stA(s);
        __half* Bs = stB(s);
#pragma unroll
        for (int kk = 0; kk < KCH; kk += 16) {
            wmma::fragment<wmma::matrix_a, 16, 16, 16, __half, wmma::row_major> af[4];
            wmma::fragment<wmma::matrix_b, 16, 16, 16, __half, wmma::col_major> bf[2];
#pragma unroll
            for (int q = 0; q < 4; q++)
                wmma::load_matrix_sync(af[q], &As[(wy * 64 + q * 16) * KPAD + kk], KPAD);
#pragma unroll
            for (int q = 0; q < 2; q++)
                wmma::load_matrix_sync(bf[q], &Bs[(wx * 32 + q * 16) * KPAD + kk], KPAD);
#pragma unroll
            for (int q = 0; q < 4; q++)
#pragma unroll
                for (int r = 0; r < 2; r++)
                    wmma::mma_sync(acc[q][r], af[q], bf[r], acc[q][r]);
        }
        __syncthreads();
    }

#pragma unroll
    for (int i = 0; i < 4; i++) {
        int row0 = m0 + wy * 64 + i * 16;
#pragma unroll
        for (int j = 0; j < 2; j++) {
            int col0 = n0 + wx * 32 + j * 16;
            if (MODE == 0) {
                int b = row0 >> 10, n = row0 & 1023;
                int which = col0 / 768;
                int c = col0 - which * 768;
                int h = c >> 6, d0 = c & 63;
                size_t off = ((size_t)(b * NHEAD + h) << 16) + (n << 6) + d0;
                __half* dsth = (which == 0 ? g_Qh : (which == 1 ? g_Kh : g_Vh)) + off;
                float* stw = &u.stg[w][0];
                wmma::store_matrix_sync(stw, acc[i][j], 18, wmma::mem_row_major);
                __syncwarp();
                int rr = lid >> 1, cc = (lid & 1) * 8;
                float* sp = stw + rr * 18 + cc;
                __half2 h0 = __floats2half2_rn(sp[0], sp[1]);
                __half2 h1 = __floats2half2_rn(sp[2], sp[3]);
                __half2 h2 = __floats2half2_rn(sp[4], sp[5]);
                __half2 h3 = __floats2half2_rn(sp[6], sp[7]);
                __half2* dp = (__half2*)(dsth + (size_t)rr * 64 + cc);
                dp[0] = h0; dp[1] = h1; dp[2] = h2; dp[3] = h3;
                __syncwarp();
            } else {
                wmma::store_matrix_sync(outp + (size_t)row0 * 768 + col0, acc[i][j],
                                        768, wmma::mem_row_major);
            }
        }
    }
}

// ============================================================
// learned LR: eta = sigmoid(x·w_h + b_h)/64 — smem-cached weights
// ============================================================
__global__ __launch_bounds__(256) void lr_kernel2(
    const float* __restrict__ x, const float* __restrict__ lrw,
    const float* __restrict__ lrb)
{
    __shared__ float ws[12 * 768];
    __shared__ float lb[12];
    int t = threadIdx.x, w = t >> 5, l = t & 31;
    for (int i = t; i < 12 * 768; i += 256) ws[i] = lrw[i];
    if (t < 12) lb[t] = lrb[t];
    __syncthreads();

    int rowbase = blockIdx.x * 64 + w * 8;
    for (int rr = 0; rr < 8; rr++) {
        int row = rowbase + rr;
        const float* xr = x + (size_t)row * 768;
        float xv[24];
#pragma unroll
        for (int k = 0; k < 24; k++) xv[k] = xr[l + k * 32];
#pragma unroll
        for (int h = 0; h < 12; h++) {
            float s = 0.f;
#pragma unroll
            for (int k = 0; k < 24; k++) s = fmaf(xv[k], ws[h * 768 + l + k * 32], s);
            s = warp_sum(s);
            if (l == 0) {
                float v = 1.f / (1.f + expf(-(s + lb[h])));
                int b = row >> 10, n = row & 1023;
                g_eta[(b * NHEAD + h) * 1024 + n] = v * (1.f / 64.f);
            }
        }
    }
}

// ============================================================
// phase1 (tensor cores, 4-way split): block = (bh, part), 256 rows.
// ============================================================
__global__ __launch_bounds__(256) void ttt_phase1_tc(
    const float* __restrict__ W1, const float* __restrict__ b1,
    const float* __restrict__ gamma, const float* __restrict__ beta)
{
    int bh = blockIdx.x >> 2, part = blockIdx.x & 3;
    int h = bh % NHEAD;
    __shared__ __half W1h[64 * 72];
    __shared__ float zs[8][16 * 68];
    __shared__ float b1s[64], gs[64], bs[64];
    __shared__ float gbacc[8 * 64];
    int t = threadIdx.x, w = t >> 5, l = t & 31;

    for (int i = t; i < 4096; i += 256) {
        int r = i >> 6, c = i & 63;
        W1h[r * 72 + c] = __float2half(W1[h * 4096 + i]);
    }
    if (t < 64) {
        b1s[t] = b1[h * 64 + t];
        gs[t]  = gamma[h * 64 + t];
        bs[t]  = beta[h * 64 + t];
    }
    __syncthreads();

    const __half* Kh = g_Kh + (size_t)bh * TOKHD;
    const __half* Vh = g_Vh + (size_t)bh * TOKHD;
    __half* Gh = g_Gh + (size_t)bh * TOKHD;
    const float* etap = g_eta + bh * 1024;

    float gb0 = 0.f, gb1 = 0.f;
    for (int s = 0; s < 2; s++) {
        int row0 = part * 256 + (s * 8 + w) * 16;
        wmma::fragment<wmma::accumulator, 16, 16, 16, float> acc[4];
#pragma unroll
        for (int n = 0; n < 4; n++) wmma::fill_fragment(acc[n], 0.f);
#pragma unroll
        for (int k = 0; k < 4; k++) {
            wmma::fragment<wmma::matrix_a, 16, 16, 16, __half, wmma::row_major> af;
            wmma::load_matrix_sync(af, Kh + (size_t)row0 * 64 + k * 16, 64);
#pragma unroll
            for (int n = 0; n < 4; n++) {
                wmma::fragment<wmma::matrix_b, 16, 16, 16, __half, wmma::row_major> bf;
                wmma::load_matrix_sync(bf, &W1h[(k * 16) * 72 + n * 16], 72);
                wmma::mma_sync(acc[n], af, bf, acc[n]);
            }
        }
#pragma unroll
        for (int n = 0; n < 4; n++)
            wmma::store_matrix_sync(&zs[w][n * 16], acc[n], 68, wmma::mem_row_major);
        __syncwarp();

#pragma unroll
        for (int r = 0; r < 16; r++) {
            int row = row0 + r;
            float z0 = zs[w][r * 68 + l] + b1s[l];
            float z1 = zs[w][r * 68 + l + 32] + b1s[l + 32];
            float mu = warp_sum(z0 + z1) * (1.f / 64.f);
            float d0 = z0 - mu, d1 = z1 - mu;
            float var = warp_sum(d0 * d0 + d1 * d1) * (1.f / 64.f);
            float rstd = rsqrtf(var + 1e-6f);
            float xh0 = d0 * rstd, xh1 = d1 * rstd;
            float xk0 = __half2float(Kh[row * 64 + l]);
            float xk1 = __half2float(Kh[row * 64 + l + 32]);
            float xv0 = __half2float(Vh[row * 64 + l]);
            float xv1 = __half2float(Vh[row * 64 + l + 32]);
            float go0 = gs[l] * xh0 + bs[l] - (xv0 - xk0);
            float go1 = gs[l + 32] * xh1 + bs[l + 32] - (xv1 - xk1);
            float gg0 = go0 * gs[l], gg1 = go1 * gs[l + 32];
            float sg  = warp_sum(gg0 + gg1);
            float sgx = warp_sum(gg0 * xh0 + gg1 * xh1);
            float sc  = etap[row] * rstd * (1.f / 64.f) * (1.f / 1024.f);
            float gf0 = (64.f * gg0 - sg - xh0 * sgx) * sc;
            float gf1 = (64.f * gg1 - sg - xh1 * sgx) * sc;
            Gh[row * 64 + l]      = __float2half(gf0 * 1024.f);
            Gh[row * 64 + l + 32] = __float2half(gf1 * 1024.f);
            gb0 += gf0; gb1 += gf1;
        }
    }
    gbacc[w * 64 + l] = gb0;
    gbacc[w * 64 + l + 32] = gb1;
    __syncthreads();
    if (t < 64) {
        float s = 0.f;
#pragma unroll
        for (int ww = 0; ww < 8; ww++) s += gbacc[ww * 64 + t];
        g_b1part[(bh * 4 + part) * 64 + t] = s;
    }
}

// ============================================================
// gradw part (4-way K split): partial XK^T @ g -> g_W1part (fp32)
// ============================================================
__global__ __launch_bounds__(256) void ttt_gradw_part()
{
    int bh = blockIdx.x >> 2, kp = blockIdx.x & 3;
    __shared__ float parts[8][16 * 68];
    int t = threadIdx.x, w = t >> 5;
    int wt = w & 3, kh = w >> 2;

    const __half* Kh = g_Kh + (size_t)bh * TOKHD + kp * 256 * 64;
    const __half* Gh = g_Gh + (size_t)bh * TOKHD + kp * 256 * 64;

    wmma::fragment<wmma::accumulator, 16, 16, 16, float> acc[4];
#pragma unroll
    for (int n = 0; n < 4; n++) wmma::fill_fragment(acc[n], 0.f);

#pragma unroll
    for (int ks = 0; ks < 8; ks++) {
        int k = kh * 128 + ks * 16;
        wmma::fragment<wmma::matrix_a, 16, 16, 16, __half, wmma::col_major> af;
        wmma::load_matrix_sync(af, Kh + (size_t)k * 64 + wt * 16, 64);
#pragma unroll
        for (int n = 0; n < 4; n++) {
            wmma::fragment<wmma::matrix_b, 16, 16, 16, __half, wmma::row_major> bf;
            wmma::load_matrix_sync(bf, Gh + (size_t)k * 64 + n * 16, 64);
            wmma::mma_sync(acc[n], af, bf, acc[n]);
        }
    }
#pragma unroll
    for (int n = 0; n < 4; n++)
        wmma::store_matrix_sync(&parts[w][n * 16], acc[n], 68, wmma::mem_row_major);
    __syncthreads();

    float* dst = g_W1part + (size_t)(bh * 4 + kp) * 4096;
    for (int i = t; i < 4096; i += 256) {
        int d = i >> 6, e = i & 63;
        int wt2 = d >> 4, r = d & 15;
        dst[i] = parts[wt2][r * 68 + e] + parts[wt2 + 4][r * 68 + e];
    }
}

// ============================================================
// combine: W1nh = half(W1 - sum_kp(W1part)/1024); b1n = b1 - sum(b1part)
// ============================================================
__global__ __launch_bounds__(256) void ttt_combine(
    const float* __restrict__ W1, const float* __restrict__ b1)
{
    int bh = blockIdx.x;
    int h = bh % NHEAD;
    int t = threadIdx.x;
    if (t < 64) {
        float s = g_b1part[(bh * 4 + 0) * 64 + t] + g_b1part[(bh * 4 + 1) * 64 + t]
                + g_b1part[(bh * 4 + 2) * 64 + t] + g_b1part[(bh * 4 + 3) * 64 + t];
        g_b1n[bh * 64 + t] = b1[h * 64 + t] - s;
    }
    const float* p0 = g_W1part + (size_t)(bh * 4 + 0) * 4096;
    const float* p1 = g_W1part + (size_t)(bh * 4 + 1) * 4096;
    const float* p2 = g_W1part + (size_t)(bh * 4 + 2) * 4096;
    const float* p3 = g_W1part + (size_t)(bh * 4 + 3) * 4096;
    for (int i = t; i < 4096; i += 256) {
        float s = p0[i] + p1[i] + p2[i] + p3[i];
        g_W1nh[(size_t)bh * 4096 + i] =
            __float2half(W1[h * 4096 + i] - s * (1.f / 1024.f));
    }
}

// ============================================================
// phase3 (tensor cores, 4-way split): Z = XQ_h @ W1n_h + b1n,
// fp32 LN fwd, out = XQ_h + y -> g_XQWh (half, [B,N,C]).
// ============================================================
__global__ __launch_bounds__(256) void ttt_phase3_tc(
    const float* __restrict__ gamma, const float* __restrict__ beta)
{
    int bh = blockIdx.x >> 2, part = blockIdx.x & 3;
    int h = bh % NHEAD, b = bh / NHEAD;
    __shared__ __half W1h[64 * 72];
    __shared__ float zs[8][16 * 68];
    __shared__ float b1s[64], gs[64], bs[64];
    int t = threadIdx.x, w = t >> 5, l = t & 31;

    for (int i = t; i < 4096; i += 256) {
        int r = i >> 6, c = i & 63;
        W1h[r * 72 + c] = g_W1nh[(size_t)bh * 4096 + i];
    }
    if (t < 64) {
        b1s[t] = g_b1n[bh * 64 + t];
        gs[t]  = gamma[h * 64 + t];
        bs[t]  = beta[h * 64 + t];
    }
    __syncthreads();

    const __half* Qh = g_Qh + (size_t)bh * TOKHD;
    __half* Op = g_XQWh + (size_t)b * 1024 * CDIM;

    for (int s = 0; s < 2; s++) {
        int row0 = part * 256 + (s * 8 + w) * 16;
        wmma::fragment<wmma::accumulator, 16, 16, 16, float> acc[4];
#pragma unroll
        for (int n = 0; n < 4; n++) wmma::fill_fragment(acc[n], 0.f);
#pragma unroll
        for (int k = 0; k < 4; k++) {
            wmma::fragment<wmma::matrix_a, 16, 16, 16, __half, wmma::row_major> af;
            wmma::load_matrix_sync(af, Qh + (size_t)row0 * 64 + k * 16, 64);
#pragma unroll
            for (int n = 0; n < 4; n++) {
                wmma::fragment<wmma::matrix_b, 16, 16, 16, __half, wmma::row_major> bf;
                wmma::load_matrix_sync(bf, &W1h[(k * 16) * 72 + n * 16], 72);
                wmma::mma_sync(acc[n], af, bf, acc[n]);
            }
        }
#pragma unroll
        for (int n = 0; n < 4; n++)
            wmma::store_matrix_sync(&zs[w][n * 16], acc[n], 68, wmma::mem_row_major);
        __syncwarp();

#pragma unroll
        for (int r = 0; r < 16; r++) {
            int row = row0 + r;
            float z0 = zs[w][r * 68 + l] + b1s[l];
            float z1 = zs[w][r * 68 + l + 32] + b1s[l + 32];
            float mu = warp_sum(z0 + z1) * (1.f / 64.f);
            float d0 = z0 - mu, d1 = z1 - mu;
            float var = warp_sum(d0 * d0 + d1 * d1) * (1.f / 64.f);
            float rstd = rsqrtf(var + 1e-6f);
            float y0 = gs[l] * (d0 * rstd) + bs[l];
            float y1 = gs[l + 32] * (d1 * rstd) + bs[l + 32];
            float xq0 = __half2float(Qh[row * 64 + l]);
            float xq1 = __half2float(Qh[row * 64 + l + 32]);
            Op[row * CDIM + h * 64 + l]      = __float2half(xq0 + y0);
            Op[row * CDIM + h * 64 + l + 32] = __float2half(xq1 + y1);
        }
    }
}

// ============================================================
extern "C" void kernel_launch(void* const* d_in, const int* in_sizes, int n_in,
                              void* d_out, int out_size)
{
    (void)in_sizes; (void)n_in; (void)out_size;
    const float* x     = (const float*)d_in[0];
    const float* qkvw  = (const float*)d_in[1];
    const float* qb    = (const float*)d_in[2];
    const float* vb    = (const float*)d_in[3];
    const float* pw    = (const float*)d_in[4];
    const float* pb    = (const float*)d_in[5];
    const float* lrw   = (const float*)d_in[6];
    const float* lrb   = (const float*)d_in[7];
    const float* gamma = (const float*)d_in[8];
    const float* beta  = (const float*)d_in[9];
    const float* W1    = (const float*)d_in[10];
    const float* b1    = (const float*)d_in[11];
    float* out = (float*)d_out;

    cudaFuncSetAttribute(gemm_fp16<0>, cudaFuncAttributeMaxDynamicSharedMemorySize, GEMM_SMEM);
    cudaFuncSetAttribute(gemm_fp16<1>, cudaFuncAttributeMaxDynamicSharedMemorySize, GEMM_SMEM);

    __half *Xh, *Wqh, *Wph, *XQWh;
    cudaGetSymbolAddress((void**)&Xh, g_Xh);
    cudaGetSymbolAddress((void**)&Wqh, g_Wqh);
    cudaGetSymbolAddress((void**)&Wph, g_Wph);
    cudaGetSymbolAddress((void**)&XQWh, g_XQWh);

    f2h_pass<<<(6291456 + 255) / 256, 256>>>(x, Xh, 6291456);
    f2h_pass<<<(884736 + 255) / 256, 256>>>(qkvw, Wqh, 884736);
    f2h_pass<<<(294912 + 255) / 256, 256>>>(pw, Wph, 294912);

    gemm_fp16<0><<<dim3(18, 128), 256, GEMM_SMEM>>>(Xh, Wqh, qb, vb, nullptr);

    lr_kernel2<<<256, 256>>>(x, lrw, lrb);
    ttt_phase1_tc<<<768, 256>>>(W1, b1, gamma, beta);
    ttt_gradw_part<<<768, 256>>>();
    ttt_combine<<<192, 256>>>(W1, b1);
    ttt_phase3_tc<<<768, 256>>>(gamma, beta);

    gemm_fp16<1><<<dim3(6, 128), 256, GEMM_SMEM>>>(XQWh, Wph, pb, nullptr, out);
}

// round 10
// speedup vs baseline: 4.7206x; 1.0525x over previous
#include <cuda_runtime.h>
#include <cuda_fp16.h>
#include <mma.h>
#include <math.h>
#include <stdint.h>

using namespace nvcuda;

// Problem constants: B=16, N=1024, C=768, H=12, HD=64, one mini-batch (m=1024)
#define NTOK   16384
#define CDIM   768
#define NHEAD  12
#define HD     64
#define BH     192
#define TOKHD  65536          // 1024*64 per (b,h)

// ---- scratch (static device globals; no allocations anywhere) ----
__device__ float  g_eta[196608];     // [B,H,N]
__device__ float  g_b1n[12288];      // [BH,64]
__device__ float  g_b1part[49152];   // [BH,4,64] partial b1 grad sums
__device__ float  g_W1part[3145728]; // [BH,4,64,64] partial W1 grads
__device__ __half g_Xh[12582912];    // half(x) [16384,768]
__device__ __half g_Wqh[1769472];    // half(qkv_weight) [2304,768]
__device__ __half g_Wph[589824];     // half(proj_weight) [768,768]
__device__ __half g_XQWh[12582912];  // half pre-projection [B,N,C]
__device__ __half g_Qh[12582912];    // half Q [B,H,N,64]
__device__ __half g_Kh[12582912];    // half K
__device__ __half g_Vh[12582912];    // half V
__device__ __half g_Gh[12582912];    // half g scaled by 1024
__device__ __half g_W1nh[786432];    // half W1n [BH,64,64]

__device__ __forceinline__ float warp_sum(float v) {
#pragma unroll
    for (int o = 16; o > 0; o >>= 1) v += __shfl_xor_sync(0xffffffffu, v, o);
    return v;
}
// paired reduction: two independent chains interleave, hiding shfl latency
__device__ __forceinline__ void warp_sum2(float& a, float& b) {
#pragma unroll
    for (int o = 16; o > 0; o >>= 1) {
        a += __shfl_xor_sync(0xffffffffu, a, o);
        b += __shfl_xor_sync(0xffffffffu, b, o);
    }
}
__device__ __forceinline__ uint32_t smem_u32(const void* p) {
    uint32_t a;
    asm("{ .reg .u64 t; cvta.to.shared.u64 t, %1; cvt.u32.u64 %0, t; }"
        : "=r"(a) : "l"(p));
    return a;
}
__device__ __forceinline__ void cp16(uint32_t dst, const void* src) {
    asm volatile("cp.async.cg.shared.global [%0], [%1], 16;" :: "r"(dst), "l"(src));
}
__device__ __forceinline__ void cp_commit() {
    asm volatile("cp.async.commit_group;" ::: "memory");
}
template <int N> __device__ __forceinline__ void cp_wait() {
    asm volatile("cp.async.wait_group %0;" :: "n"(N) : "memory");
}

// ============================================================
// fp32 -> fp16 conversion pass (half2 stores) — weights only now
// ============================================================
__global__ void f2h_pass(const float* __restrict__ in, __half* __restrict__ out, int n2)
{
    int i = blockIdx.x * blockDim.x + threadIdx.x;
    if (i < n2) {
        float2 v = ((const float2*)in)[i];
        ((__half2*)out)[i] = __floats2half2_rn(v.x, v.y);
    }
}

// ============================================================
// fp16 wmma GEMM (round-9 config): C = A[M,768] @ W[N,768]^T (+bias)
// Tile 128x128, 8 warps (64x32), K chunks of 32, 3-stage cp.async.
// MODE 0: half-only Q/K/V out; MODE 1: fp32 out.
// ============================================================
#define KCH 32
#define KPAD 40
#define BUF_HALFS (128 * KPAD)
#define NSTAGE 3
#define GEMM_SMEM (NSTAGE * 2 * BUF_HALFS * 2)

template <int MODE>
__global__ __launch_bounds__(256, 2) void gemm_fp16(
    const __half* __restrict__ A, const __half* __restrict__ Bw,
    const float* __restrict__ bias0, const float* __restrict__ bias1,
    float* __restrict__ outp)
{
    extern __shared__ __half hsm[];
    __shared__ union {
        float bias2d[16][132];
        float stg[8][16 * 18];
    } u;

    int t = threadIdx.x;
    int w = t >> 5, lid = t & 31;
    int wy = w >> 2, wx = w & 3;
    int m0 = blockIdx.y * 128, n0 = blockIdx.x * 128;

    if (t < 128) {
        int col = n0 + t;
        float bv;
        if (MODE == 0) {
            int which = col / 768, c = col - which * 768;
            bv = (which == 0) ? bias0[c] : ((which == 2) ? bias1[c] : 0.f);
        } else bv = bias0[col];
#pragma unroll
        for (int r = 0; r < 16; r++) u.bias2d[r][t] = bv;
    }
    __syncthreads();

    wmma::fragment<wmma::accumulator, 16, 16, 16, float> acc[4][2];
#pragma unroll
    for (int i = 0; i < 4; i++)
#pragma unroll
        for (int j = 0; j < 2; j++)
            wmma::load_matrix_sync(acc[i][j], &u.bias2d[0][wx * 32 + j * 16], 132,
                                   wmma::mem_row_major);
    __syncthreads();

    const __half* gA = A + (size_t)m0 * 768;
    const __half* gB = Bw + (size_t)n0 * 768;

    auto stA = [&](int s) -> __half* { return hsm + s * 2 * BUF_HALFS; };
    auto stB = [&](int s) -> __half* { return hsm + s * 2 * BUF_HALFS + BUF_HALFS; };

    auto load_chunk = [&](int kc, int s) {
        uint32_t aS = smem_u32(stA(s));
        uint32_t bS = smem_u32(stB(s));
#pragma unroll
        for (int j = 0; j < 2; j++) {
            int idx = t + j * 256;
            int row = idx >> 2, c4 = idx & 3;
            cp16(aS + row * (KPAD * 2) + c4 * 16,
                 gA + (size_t)row * 768 + kc * KCH + c4 * 8);
            cp16(bS + row * (KPAD * 2) + c4 * 16,
                 gB + (size_t)row * 768 + kc * KCH + c4 * 8);
        }
        cp_commit();
    };

    const int NCHUNK = 24;
    load_chunk(0, 0);
    load_chunk(1, 1);
    for (int i = 0; i < NCHUNK; i++) {
        int s = i % NSTAGE;
        if (i + 2 < NCHUNK) { load_chunk(i + 2, (i + 2) % NSTAGE); cp_wait<2>(); }
        else if (i + 1 < NCHUNK) cp_wait<1>();
        else cp_wait<0>();
        __syncthreads();

        __half* As = stA(s);
        __half* Bs = stB(s);
#pragma unroll
        for (int kk = 0; kk < KCH; kk += 16) {
            wmma::fragment<wmma::matrix_a, 16, 16, 16, __half, wmma::row_major> af[4];
            wmma::fragment<wmma::matrix_b, 16, 16, 16, __half, wmma::col_major> bf[2];
#pragma unroll
            for (int q = 0; q < 4; q++)
                wmma::load_matrix_sync(af[q], &As[(wy * 64 + q * 16) * KPAD + kk], KPAD);
#pragma unroll
            for (int q = 0; q < 2; q++)
                wmma::load_matrix_sync(bf[q], &Bs[(wx * 32 + q * 16) * KPAD + kk], KPAD);
#pragma unroll
            for (int q = 0; q < 4; q++)
#pragma unroll
                for (int r = 0; r < 2; r++)
                    wmma::mma_sync(acc[q][r], af[q], bf[r], acc[q][r]);
        }
        __syncthreads();
    }

#pragma unroll
    for (int i = 0; i < 4; i++) {
        int row0 = m0 + wy * 64 + i * 16;
#pragma unroll
        for (int j = 0; j < 2; j++) {
            int col0 = n0 + wx * 32 + j * 16;
            if (MODE == 0) {
                int b = row0 >> 10, n = row0 & 1023;
                int which = col0 / 768;
                int c = col0 - which * 768;
                int h = c >> 6, d0 = c & 63;
                size_t off = ((size_t)(b * NHEAD + h) << 16) + (n << 6) + d0;
                __half* dsth = (which == 0 ? g_Qh : (which == 1 ? g_Kh : g_Vh)) + off;
                float* stw = &u.stg[w][0];
                wmma::store_matrix_sync(stw, acc[i][j], 18, wmma::mem_row_major);
                __syncwarp();
                int rr = lid >> 1, cc = (lid & 1) * 8;
                float* sp = stw + rr * 18 + cc;
                __half2 h0 = __floats2half2_rn(sp[0], sp[1]);
                __half2 h1 = __floats2half2_rn(sp[2], sp[3]);
                __half2 h2 = __floats2half2_rn(sp[4], sp[5]);
                __half2 h3 = __floats2half2_rn(sp[6], sp[7]);
                __half2* dp = (__half2*)(dsth + (size_t)rr * 64 + cc);
                dp[0] = h0; dp[1] = h1; dp[2] = h2; dp[3] = h3;
                __syncwarp();
            } else {
                wmma::store_matrix_sync(outp + (size_t)row0 * 768 + col0, acc[i][j],
                                        768, wmma::mem_row_major);
            }
        }
    }
}

// ============================================================
// learned LR + fused f2h(x): eta = sigmoid(x·w_h+b_h)/64 and Xh = half(x)
// ============================================================
__global__ __launch_bounds__(256) void lr_kernel2(
    const float* __restrict__ x, const float* __restrict__ lrw,
    const float* __restrict__ lrb, __half* __restrict__ Xh)
{
    __shared__ float ws[12 * 768];
    __shared__ float lb[12];
    int t = threadIdx.x, w = t >> 5, l = t & 31;
    for (int i = t; i < 12 * 768; i += 256) ws[i] = lrw[i];
    if (t < 12) lb[t] = lrb[t];
    __syncthreads();

    int rowbase = blockIdx.x * 64 + w * 8;
    for (int rr = 0; rr < 8; rr++) {
        int row = rowbase + rr;
        const float* xr = x + (size_t)row * 768;
        float xv[24];
#pragma unroll
        for (int k = 0; k < 24; k++) xv[k] = xr[l + k * 32];
        // fused x -> half conversion
        __half* xo = Xh + (size_t)row * 768;
#pragma unroll
        for (int k = 0; k < 24; k++) xo[l + k * 32] = __float2half(xv[k]);
#pragma unroll
        for (int h = 0; h < 12; h++) {
            float s = 0.f;
#pragma unroll
            for (int k = 0; k < 24; k++) s = fmaf(xv[k], ws[h * 768 + l + k * 32], s);
            s = warp_sum(s);
            if (l == 0) {
                float v = 1.f / (1.f + expf(-(s + lb[h])));
                int b = row >> 10, n = row & 1023;
                g_eta[(b * NHEAD + h) * 1024 + n] = v * (1.f / 64.f);
            }
        }
    }
}

// ============================================================
// phase1 (tensor cores, 4-way split) + FUSED gradw partial.
// block = (bh, part): 256 rows. Z1 = XK_h@W1_h+b1 (wmma), fp32
// LN-L2-bwd with paired reductions, g*1024 -> g_Gh, partial b1 sums,
// then partial XK^T@g for this part -> g_W1part.
// ============================================================
__global__ __launch_bounds__(256) void ttt_phase1_tc(
    const float* __restrict__ W1, const float* __restrict__ b1,
    const float* __restrict__ gamma, const float* __restrict__ beta)
{
    int bh = blockIdx.x >> 2, part = blockIdx.x & 3;
    int h = bh % NHEAD;
    __shared__ __half W1h[64 * 72];
    __shared__ float zs[8][16 * 68];          // reused as gradw 'parts'
    __shared__ float b1s[64], gs[64], bs[64];
    __shared__ float gbacc[8 * 64];
    int t = threadIdx.x, w = t >> 5, l = t & 31;

    for (int i = t; i < 4096; i += 256) {
        int r = i >> 6, c = i & 63;
        W1h[r * 72 + c] = __float2half(W1[h * 4096 + i]);
    }
    if (t < 64) {
        b1s[t] = b1[h * 64 + t];
        gs[t]  = gamma[h * 64 + t];
        bs[t]  = beta[h * 64 + t];
    }
    __syncthreads();

    const __half* Kh = g_Kh + (size_t)bh * TOKHD;
    const __half* Vh = g_Vh + (size_t)bh * TOKHD;
    __half* Gh = g_Gh + (size_t)bh * TOKHD;
    const float* etap = g_eta + bh * 1024;

    float gb0 = 0.f, gb1 = 0.f;
    for (int s = 0; s < 2; s++) {
        int row0 = part * 256 + (s * 8 + w) * 16;
        wmma::fragment<wmma::accumulator, 16, 16, 16, float> acc[4];
#pragma unroll
        for (int n = 0; n < 4; n++) wmma::fill_fragment(acc[n], 0.f);
#pragma unroll
        for (int k = 0; k < 4; k++) {
            wmma::fragment<wmma::matrix_a, 16, 16, 16, __half, wmma::row_major> af;
            wmma::load_matrix_sync(af, Kh + (size_t)row0 * 64 + k * 16, 64);
#pragma unroll
            for (int n = 0; n < 4; n++) {
                wmma::fragment<wmma::matrix_b, 16, 16, 16, __half, wmma::row_major> bf;
                wmma::load_matrix_sync(bf, &W1h[(k * 16) * 72 + n * 16], 72);
                wmma::mma_sync(acc[n], af, bf, acc[n]);
            }
        }
#pragma unroll
        for (int n = 0; n < 4; n++)
            wmma::store_matrix_sync(&zs[w][n * 16], acc[n], 68, wmma::mem_row_major);
        __syncwarp();

#pragma unroll
        for (int r = 0; r < 16; r++) {
            int row = row0 + r;
            float z0 = zs[w][r * 68 + l] + b1s[l];
            float z1 = zs[w][r * 68 + l + 32] + b1s[l + 32];
            // paired reduction: sum and sum-of-squares concurrently
            float s1 = z0 + z1, s2 = z0 * z0 + z1 * z1;
            warp_sum2(s1, s2);
            float mu = s1 * (1.f / 64.f);
            float var = s2 * (1.f / 64.f) - mu * mu;
            float rstd = rsqrtf(var + 1e-6f);
            float xh0 = (z0 - mu) * rstd, xh1 = (z1 - mu) * rstd;
            float xk0 = __half2float(Kh[row * 64 + l]);
            float xk1 = __half2float(Kh[row * 64 + l + 32]);
            float xv0 = __half2float(Vh[row * 64 + l]);
            float xv1 = __half2float(Vh[row * 64 + l + 32]);
            float go0 = gs[l] * xh0 + bs[l] - (xv0 - xk0);
            float go1 = gs[l + 32] * xh1 + bs[l + 32] - (xv1 - xk1);
            float gg0 = go0 * gs[l], gg1 = go1 * gs[l + 32];
            float sg = gg0 + gg1, sgx = gg0 * xh0 + gg1 * xh1;
            warp_sum2(sg, sgx);
            float sc = etap[row] * rstd * (1.f / 64.f) * (1.f / 1024.f);
            float gf0 = (64.f * gg0 - sg - xh0 * sgx) * sc;
            float gf1 = (64.f * gg1 - sg - xh1 * sgx) * sc;
            Gh[row * 64 + l]      = __float2half(gf0 * 1024.f);
            Gh[row * 64 + l + 32] = __float2half(gf1 * 1024.f);
            gb0 += gf0; gb1 += gf1;
        }
    }
    gbacc[w * 64 + l] = gb0;
    gbacc[w * 64 + l + 32] = gb1;
    __syncthreads();   // all 256 rows of Gh written + gbacc ready
    if (t < 64) {
        float s = 0.f;
#pragma unroll
        for (int ww = 0; ww < 8; ww++) s += gbacc[ww * 64 + t];
        g_b1part[(bh * 4 + part) * 64 + t] = s;
    }

    // ---- fused gradw partial: XK[part]^T @ g[part] (256-deep) ----
    {
        const __half* Kp2 = Kh + part * 256 * 64;
        const __half* Gp2 = Gh + part * 256 * 64;
        int wt = w & 3, kh2 = w >> 2;
        wmma::fragment<wmma::accumulator, 16, 16, 16, float> acc2[4];
#pragma unroll
        for (int n = 0; n < 4; n++) wmma::fill_fragment(acc2[n], 0.f);
#pragma unroll
        for (int ks = 0; ks < 8; ks++) {
            int k = kh2 * 128 + ks * 16;
            wmma::fragment<wmma::matrix_a, 16, 16, 16, __half, wmma::col_major> af;
            wmma::load_matrix_sync(af, Kp2 + (size_t)k * 64 + wt * 16, 64);
#pragma unroll
            for (int n = 0; n < 4; n++) {
                wmma::fragment<wmma::matrix_b, 16, 16, 16, __half, wmma::row_major> bf;
                wmma::load_matrix_sync(bf, Gp2 + (size_t)k * 64 + n * 16, 64);
                wmma::mma_sync(acc2[n], af, bf, acc2[n]);
            }
        }
        __syncthreads();   // zs free for reuse
#pragma unroll
        for (int n = 0; n < 4; n++)
            wmma::store_matrix_sync(&zs[w][n * 16], acc2[n], 68, wmma::mem_row_major);
        __syncthreads();

        float* dst = g_W1part + (size_t)(bh * 4 + part) * 4096;
        for (int i = t; i < 4096; i += 256) {
            int d = i >> 6, e = i & 63;
            int wt2 = d >> 4, r = d & 15;
            dst[i] = zs[wt2][r * 68 + e] + zs[wt2 + 4][r * 68 + e];
        }
    }
}

// ============================================================
// combine: W1nh = half(W1 - sum_kp(W1part)/1024); b1n = b1 - sum(b1part)
// ============================================================
__global__ __launch_bounds__(256) void ttt_combine(
    const float* __restrict__ W1, const float* __restrict__ b1)
{
    int bh = blockIdx.x;
    int h = bh % NHEAD;
    int t = threadIdx.x;
    if (t < 64) {
        float s = g_b1part[(bh * 4 + 0) * 64 + t] + g_b1part[(bh * 4 + 1) * 64 + t]
                + g_b1part[(bh * 4 + 2) * 64 + t] + g_b1part[(bh * 4 + 3) * 64 + t];
        g_b1n[bh * 64 + t] = b1[h * 64 + t] - s;
    }
    const float* p0 = g_W1part + (size_t)(bh * 4 + 0) * 4096;
    const float* p1 = g_W1part + (size_t)(bh * 4 + 1) * 4096;
    const float* p2 = g_W1part + (size_t)(bh * 4 + 2) * 4096;
    const float* p3 = g_W1part + (size_t)(bh * 4 + 3) * 4096;
    for (int i = t; i < 4096; i += 256) {
        float s = p0[i] + p1[i] + p2[i] + p3[i];
        g_W1nh[(size_t)bh * 4096 + i] =
            __float2half(W1[h * 4096 + i] - s * (1.f / 1024.f));
    }
}

// ============================================================
// phase3 (tensor cores, 4-way split): Z = XQ_h @ W1n_h + b1n,
// fp32 LN fwd (paired reduction), out = XQ_h + y -> g_XQWh.
// ============================================================
__global__ __launch_bounds__(256) void ttt_phase3_tc(
    const float* __restrict__ gamma, const float* __restrict__ beta)
{
    int bh = blockIdx.x >> 2, part = blockIdx.x & 3;
    int h = bh % NHEAD, b = bh / NHEAD;
    __shared__ __half W1h[64 * 72];
    __shared__ float zs[8][16 * 68];
    __shared__ float b1s[64], gs[64], bs[64];
    int t = threadIdx.x, w = t >> 5, l = t & 31;

    for (int i = t; i < 4096; i += 256) {
        int r = i >> 6, c = i & 63;
        W1h[r * 72 + c] = g_W1nh[(size_t)bh * 4096 + i];
    }
    if (t < 64) {
        b1s[t] = g_b1n[bh * 64 + t];
        gs[t]  = gamma[h * 64 + t];
        bs[t]  = beta[h * 64 + t];
    }
    __syncthreads();

    const __half* Qh = g_Qh + (size_t)bh * TOKHD;
    __half* Op = g_XQWh + (size_t)b * 1024 * CDIM;

    for (int s = 0; s < 2; s++) {
        int row0 = part * 256 + (s * 8 + w) * 16;
        wmma::fragment<wmma::accumulator, 16, 16, 16, float> acc[4];
#pragma unroll
        for (int n = 0; n < 4; n++) wmma::fill_fragment(acc[n], 0.f);
#pragma unroll
        for (int k = 0; k < 4; k++) {
            wmma::fragment<wmma::matrix_a, 16, 16, 16, __half, wmma::row_major> af;
            wmma::load_matrix_sync(af, Qh + (size_t)row0 * 64 + k * 16, 64);
#pragma unroll
            for (int n = 0; n < 4; n++) {
                wmma::fragment<wmma::matrix_b, 16, 16, 16, __half, wmma::row_major> bf;
                wmma::load_matrix_sync(bf, &W1h[(k * 16) * 72 + n * 16], 72);
                wmma::mma_sync(acc[n], af, bf, acc[n]);
            }
        }
#pragma unroll
        for (int n = 0; n < 4; n++)
            wmma::store_matrix_sync(&zs[w][n * 16], acc[n], 68, wmma::mem_row_major);
        __syncwarp();

#pragma unroll
        for (int r = 0; r < 16; r++) {
            int row = row0 + r;
            float z0 = zs[w][r * 68 + l] + b1s[l];
            float z1 = zs[w][r * 68 + l + 32] + b1s[l + 32];
            float s1 = z0 + z1, s2 = z0 * z0 + z1 * z1;
            warp_sum2(s1, s2);
            float mu = s1 * (1.f / 64.f);
            float var = s2 * (1.f / 64.f) - mu * mu;
            float rstd = rsqrtf(var + 1e-6f);
            float y0 = gs[l] * ((z0 - mu) * rstd) + bs[l];
            float y1 = gs[l + 32] * ((z1 - mu) * rstd) + bs[l + 32];
            float xq0 = __half2float(Qh[row * 64 + l]);
            float xq1 = __half2float(Qh[row * 64 + l + 32]);
            Op[row * CDIM + h * 64 + l]      = __float2half(xq0 + y0);
            Op[row * CDIM + h * 64 + l + 32] = __float2half(xq1 + y1);
        }
    }
}

// ============================================================
extern "C" void kernel_launch(void* const* d_in, const int* in_sizes, int n_in,
                              void* d_out, int out_size)
{
    (void)in_sizes; (void)n_in; (void)out_size;
    const float* x     = (const float*)d_in[0];
    const float* qkvw  = (const float*)d_in[1];
    const float* qb    = (const float*)d_in[2];
    const float* vb    = (const float*)d_in[3];
    const float* pw    = (const float*)d_in[4];
    const float* pb    = (const float*)d_in[5];
    const float* lrw   = (const float*)d_in[6];
    const float* lrb   = (const float*)d_in[7];
    const float* gamma = (const float*)d_in[8];
    const float* beta  = (const float*)d_in[9];
    const float* W1    = (const float*)d_in[10];
    const float* b1    = (const float*)d_in[11];
    float* out = (float*)d_out;

    cudaFuncSetAttribute(gemm_fp16<0>, cudaFuncAttributeMaxDynamicSharedMemorySize, GEMM_SMEM);
    cudaFuncSetAttribute(gemm_fp16<1>, cudaFuncAttributeMaxDynamicSharedMemorySize, GEMM_SMEM);

    __half *Xh, *Wqh, *Wph, *XQWh;
    cudaGetSymbolAddress((void**)&Xh, g_Xh);
    cudaGetSymbolAddress((void**)&Wqh, g_Wqh);
    cudaGetSymbolAddress((void**)&Wph, g_Wph);
    cudaGetSymbolAddress((void**)&XQWh, g_XQWh);

    // lr first: produces g_eta AND g_Xh (fused f2h of x)
    lr_kernel2<<<256, 256>>>(x, lrw, lrb, Xh);
    f2h_pass<<<(884736 + 255) / 256, 256>>>(qkvw, Wqh, 884736);
    f2h_pass<<<(294912 + 255) / 256, 256>>>(pw, Wph, 294912);

    gemm_fp16<0><<<dim3(18, 128), 256, GEMM_SMEM>>>(Xh, Wqh, qb, vb, nullptr);

    ttt_phase1_tc<<<768, 256>>>(W1, b1, gamma, beta);   // includes gradw partials
    ttt_combine<<<192, 256>>>(W1, b1);
    ttt_phase3_tc<<<768, 256>>>(gamma, beta);

    gemm_fp16<1><<<dim3(6, 128), 256, GEMM_SMEM>>>(XQWh, Wph, pb, nullptr, out);
}